// round 1
// baseline (speedup 1.0000x reference)
#include <cuda_runtime.h>

// Problem constants
#define BATCH 4
#define LSEQ  2048
#define CDIM  1024
#define NHEAD 16
#define DHEAD 64
#define MROWS (BATCH * LSEQ)   // 8192

// Scratch (device globals: allocation-free per harness rules)
__device__ float g_q[BATCH * NHEAD * LSEQ * DHEAD];    // [b][h][l][d]
__device__ float g_k[BATCH * NHEAD * LSEQ * DHEAD];
__device__ float g_v[BATCH * NHEAD * LSEQ * DHEAD];
__device__ float g_ctx[MROWS * CDIM];                  // [b*l][c]

// ---------------------------------------------------------------------------
// NT GEMM: C[m][n] = sum_k A[m][k] * Bw[n][k]
// MODE 0: A = input param, epilogue scatters into g_q/g_k/g_v ([b][h][l][d])
// MODE 1: A = g_ctx, epilogue writes plain row-major Cout [8192][1024]
// Tile: BM=128, BN=128, BK=16; 256 threads; 8x8 per-thread micro-tile.
// ---------------------------------------------------------------------------
template <int MODE>
__global__ __launch_bounds__(256) void gemm_nt_kernel(
    const float* __restrict__ Ain,
    const float* __restrict__ Bw,
    float* __restrict__ Cout)
{
    __shared__ float As[16][128];
    __shared__ float Bs[16][128];

    const float* __restrict__ A = (MODE == 0) ? Ain : g_ctx;

    const int tid = threadIdx.x;
    const int tx = tid & 15;        // 0..15
    const int ty = tid >> 4;        // 0..15
    const int m0 = blockIdx.y * 128;
    const int n0 = blockIdx.x * 128;

    // loader indices: 128 rows x 16 k per operand, float4 along k
    const int lr = tid >> 2;            // 0..63
    const int lk = (tid & 3) * 4;       // 0,4,8,12

    float acc[8][8];
#pragma unroll
    for (int i = 0; i < 8; i++)
#pragma unroll
        for (int j = 0; j < 8; j++) acc[i][j] = 0.f;

    for (int k0 = 0; k0 < 1024; k0 += 16) {
        float4 a0 = *(const float4*)&A [(size_t)(m0 + lr)      * 1024 + k0 + lk];
        float4 a1 = *(const float4*)&A [(size_t)(m0 + lr + 64) * 1024 + k0 + lk];
        float4 b0 = *(const float4*)&Bw[(size_t)(n0 + lr)      * 1024 + k0 + lk];
        float4 b1 = *(const float4*)&Bw[(size_t)(n0 + lr + 64) * 1024 + k0 + lk];

        __syncthreads();  // previous iteration's readers done
        As[lk + 0][lr] = a0.x; As[lk + 1][lr] = a0.y;
        As[lk + 2][lr] = a0.z; As[lk + 3][lr] = a0.w;
        As[lk + 0][lr + 64] = a1.x; As[lk + 1][lr + 64] = a1.y;
        As[lk + 2][lr + 64] = a1.z; As[lk + 3][lr + 64] = a1.w;
        Bs[lk + 0][lr] = b0.x; Bs[lk + 1][lr] = b0.y;
        Bs[lk + 2][lr] = b0.z; Bs[lk + 3][lr] = b0.w;
        Bs[lk + 0][lr + 64] = b1.x; Bs[lk + 1][lr + 64] = b1.y;
        Bs[lk + 2][lr + 64] = b1.z; Bs[lk + 3][lr + 64] = b1.w;
        __syncthreads();

#pragma unroll
        for (int kk = 0; kk < 16; kk++) {
            float4 af0 = *(const float4*)&As[kk][ty * 8];
            float4 af1 = *(const float4*)&As[kk][ty * 8 + 4];
            float4 bf0 = *(const float4*)&Bs[kk][tx * 8];
            float4 bf1 = *(const float4*)&Bs[kk][tx * 8 + 4];
            float a[8] = {af0.x, af0.y, af0.z, af0.w, af1.x, af1.y, af1.z, af1.w};
            float b[8] = {bf0.x, bf0.y, bf0.z, bf0.w, bf1.x, bf1.y, bf1.z, bf1.w};
#pragma unroll
            for (int i = 0; i < 8; i++)
#pragma unroll
                for (int j = 0; j < 8; j++)
                    acc[i][j] = fmaf(a[i], b[j], acc[i][j]);
        }
    }

    if (MODE == 1) {
        // plain row-major store
#pragma unroll
        for (int i = 0; i < 8; i++) {
            const int m = m0 + ty * 8 + i;
            float* p = &Cout[(size_t)m * 1024 + n0 + tx * 8];
            *(float4*)&p[0] = make_float4(acc[i][0], acc[i][1], acc[i][2], acc[i][3]);
            *(float4*)&p[4] = make_float4(acc[i][4], acc[i][5], acc[i][6], acc[i][7]);
        }
    } else {
        // scatter into q/k/v [b][h][l][d]
        const int nbase = n0 + tx * 8;        // thread's 8 cols are contiguous
        const int which = nbase >> 10;        // 0=q 1=k 2=v (uniform per block)
        const int c = nbase & 1023;
        const int h = c >> 6;
        const int d0 = c & 63;                // d0..d0+7 within one head
        float* dst = (which == 0) ? g_q : ((which == 1) ? g_k : g_v);
#pragma unroll
        for (int i = 0; i < 8; i++) {
            const int m = m0 + ty * 8 + i;
            const int bb = m >> 11;           // /2048
            const int l = m & 2047;
            float* p = &dst[(((size_t)(bb * NHEAD + h)) * LSEQ + l) * DHEAD + d0];
            *(float4*)&p[0] = make_float4(acc[i][0], acc[i][1], acc[i][2], acc[i][3]);
            *(float4*)&p[4] = make_float4(acc[i][4], acc[i][5], acc[i][6], acc[i][7]);
        }
    }
}

// ---------------------------------------------------------------------------
// Causal flash attention, fp32. Br=Bc=64, 256 threads, 4x4 per-thread tile.
// grid: (L/64, B*H). Online softmax. Output to g_ctx[b*l][h*64+d].
// ---------------------------------------------------------------------------
#define SPAD 65
#define SMEM_ATTN (4 * 64 * SPAD * (int)sizeof(float))  // Qs,Ks,Vs,Ps

__device__ __forceinline__ float warp16_max(float v) {
#pragma unroll
    for (int off = 8; off; off >>= 1)
        v = fmaxf(v, __shfl_xor_sync(0xffffffffu, v, off));
    return v;
}
__device__ __forceinline__ float warp16_sum(float v) {
#pragma unroll
    for (int off = 8; off; off >>= 1)
        v += __shfl_xor_sync(0xffffffffu, v, off);
    return v;
}

__global__ __launch_bounds__(256) void attn_kernel()
{
    extern __shared__ float sm[];
    float* Qs = sm;
    float* Ks = sm + 64 * SPAD;
    float* Vs = sm + 2 * 64 * SPAD;
    float* Ps = sm + 3 * 64 * SPAD;

    const int tid = threadIdx.x;
    const int tx = tid & 15;   // col group
    const int ty = tid >> 4;   // row group
    const int bh = blockIdx.y;
    const int qt = blockIdx.x;
    const int qbase = qt * 64;

    const float* __restrict__ Q = g_q + (size_t)bh * LSEQ * DHEAD;
    const float* __restrict__ K = g_k + (size_t)bh * LSEQ * DHEAD;
    const float* __restrict__ V = g_v + (size_t)bh * LSEQ * DHEAD;

    // load Q tile [64][64] -> Qs padded
    const int lr = tid >> 4;          // 0..15
    const int lc = (tid & 15) * 4;    // 0..60
#pragma unroll
    for (int r = 0; r < 4; r++) {
        float4 v4 = *(const float4*)&Q[(size_t)(qbase + lr + 16 * r) * DHEAD + lc];
        float* p = &Qs[(lr + 16 * r) * SPAD + lc];
        p[0] = v4.x; p[1] = v4.y; p[2] = v4.z; p[3] = v4.w;
    }

    float Ob[4][4];
    float mrow[4], lrow[4];
#pragma unroll
    for (int i = 0; i < 4; i++) {
        mrow[i] = -1e30f; lrow[i] = 0.f;
#pragma unroll
        for (int j = 0; j < 4; j++) Ob[i][j] = 0.f;
    }
    const float scale = 0.125f;  // 1/sqrt(64)

    const int ntiles = qt + 1;   // causal: only tiles with kbase <= qbase
    for (int t = 0; t < ntiles; t++) {
        const int kbase = t * 64;

        __syncthreads();  // prior PV done (and Q store on first iter)
#pragma unroll
        for (int r = 0; r < 4; r++) {
            float4 kv = *(const float4*)&K[(size_t)(kbase + lr + 16 * r) * DHEAD + lc];
            float4 vv = *(const float4*)&V[(size_t)(kbase + lr + 16 * r) * DHEAD + lc];
            float* pk = &Ks[(lr + 16 * r) * SPAD + lc];
            float* pv = &Vs[(lr + 16 * r) * SPAD + lc];
            pk[0] = kv.x; pk[1] = kv.y; pk[2] = kv.z; pk[3] = kv.w;
            pv[0] = vv.x; pv[1] = vv.y; pv[2] = vv.z; pv[3] = vv.w;
        }
        __syncthreads();

        // S = Q K^T for this thread's 4x4 block
        float S[4][4];
#pragma unroll
        for (int i = 0; i < 4; i++)
#pragma unroll
            for (int j = 0; j < 4; j++) S[i][j] = 0.f;

#pragma unroll 8
        for (int d = 0; d < 64; d++) {
            float qa[4], kb[4];
#pragma unroll
            for (int i = 0; i < 4; i++) qa[i] = Qs[(ty * 4 + i) * SPAD + d];
#pragma unroll
            for (int j = 0; j < 4; j++) kb[j] = Ks[(tx * 4 + j) * SPAD + d];
#pragma unroll
            for (int i = 0; i < 4; i++)
#pragma unroll
                for (int j = 0; j < 4; j++)
                    S[i][j] = fmaf(qa[i], kb[j], S[i][j]);
        }

        const bool diag = (t == qt);
#pragma unroll
        for (int i = 0; i < 4; i++)
#pragma unroll
            for (int j = 0; j < 4; j++) {
                S[i][j] *= scale;
                if (diag && (kbase + tx * 4 + j > qbase + ty * 4 + i))
                    S[i][j] = -1e30f;
            }

        // online softmax per row
#pragma unroll
        for (int i = 0; i < 4; i++) {
            float rmax = fmaxf(fmaxf(S[i][0], S[i][1]), fmaxf(S[i][2], S[i][3]));
            rmax = warp16_max(rmax);
            const float mnew = fmaxf(mrow[i], rmax);
            const float alpha = __expf(mrow[i] - mnew);
            float rs = 0.f;
#pragma unroll
            for (int j = 0; j < 4; j++) {
                S[i][j] = __expf(S[i][j] - mnew);
                rs += S[i][j];
            }
            rs = warp16_sum(rs);
            lrow[i] = lrow[i] * alpha + rs;
            mrow[i] = mnew;
#pragma unroll
            for (int j = 0; j < 4; j++) {
                Ob[i][j] *= alpha;
                Ps[(ty * 4 + i) * SPAD + tx * 4 + j] = S[i][j];
            }
        }
        __syncthreads();

        // O += P V
#pragma unroll 8
        for (int n = 0; n < 64; n++) {
            float pa[4], vb[4];
#pragma unroll
            for (int i = 0; i < 4; i++) pa[i] = Ps[(ty * 4 + i) * SPAD + n];
#pragma unroll
            for (int j = 0; j < 4; j++) vb[j] = Vs[n * SPAD + tx * 4 + j];
#pragma unroll
            for (int i = 0; i < 4; i++)
#pragma unroll
                for (int j = 0; j < 4; j++)
                    Ob[i][j] = fmaf(pa[i], vb[j], Ob[i][j]);
        }
    }

    // finalize + write ctx [b*l][h*64+d]
    const int b = bh >> 4;
    const int h = bh & 15;
#pragma unroll
    for (int i = 0; i < 4; i++) {
        const float inv = 1.f / lrow[i];
        const int row = qbase + ty * 4 + i;
        float4 o = make_float4(Ob[i][0] * inv, Ob[i][1] * inv,
                               Ob[i][2] * inv, Ob[i][3] * inv);
        *(float4*)&g_ctx[((size_t)(b * LSEQ + row)) * CDIM + h * DHEAD + tx * 4] = o;
    }
}

// ---------------------------------------------------------------------------
extern "C" void kernel_launch(void* const* d_in, const int* in_sizes, int n_in,
                              void* d_out, int out_size)
{
    const float* input = (const float*)d_in[0];  // [4,2048,1024]
    const float* w_in  = (const float*)d_in[1];  // [3072,1024]
    const float* w_out = (const float*)d_in[2];  // [1024,1024]
    float* out = (float*)d_out;                  // [8192,1024]

    cudaFuncSetAttribute(attn_kernel,
                         cudaFuncAttributeMaxDynamicSharedMemorySize, SMEM_ATTN);

    // 1) QKV projection, scattered into [b][h][l][d]
    gemm_nt_kernel<0><<<dim3(3072 / 128, 8192 / 128), 256>>>(input, w_in, nullptr);

    // 2) causal flash attention -> g_ctx
    attn_kernel<<<dim3(LSEQ / 64, BATCH * NHEAD), 256, SMEM_ATTN>>>();

    // 3) output projection
    gemm_nt_kernel<1><<<dim3(1024 / 128, 8192 / 128), 256>>>(nullptr, w_out, out);
}

// round 3
// speedup vs baseline: 1.3405x; 1.3405x over previous
#include <cuda_runtime.h>
#include <cuda_bf16.h>
#include <cstdint>

// ---------------------------------------------------------------------------
// Problem constants
// ---------------------------------------------------------------------------
#define BATCH 4
#define LSEQ  2048
#define CDIM  1024
#define NHEAD 16
#define DHEAD 64
#define MROWS (BATCH * LSEQ)   // 8192
#define KDIM  1024

// ---------------------------------------------------------------------------
// Device-global scratch (allocation-free per harness rules)
// ---------------------------------------------------------------------------
__device__ __nv_bfloat16 g_in_h [MROWS * KDIM];
__device__ __nv_bfloat16 g_in_l [MROWS * KDIM];
__device__ __nv_bfloat16 g_win_h[3 * CDIM * KDIM];
__device__ __nv_bfloat16 g_win_l[3 * CDIM * KDIM];
__device__ __nv_bfloat16 g_wout_h[CDIM * KDIM];
__device__ __nv_bfloat16 g_wout_l[CDIM * KDIM];
__device__ float g_q[BATCH * NHEAD * LSEQ * DHEAD];   // [b][h][l][d] fp32
__device__ float g_k[BATCH * NHEAD * LSEQ * DHEAD];
__device__ float g_v[BATCH * NHEAD * LSEQ * DHEAD];
__device__ __nv_bfloat16 g_ctx_h[MROWS * CDIM];
__device__ __nv_bfloat16 g_ctx_l[MROWS * CDIM];

// ---------------------------------------------------------------------------
// Baseline-PTX tensor helpers (compute_103-safe: mma.sync + ldmatrix only)
// ---------------------------------------------------------------------------
__device__ __forceinline__ uint32_t smem_u32(const void* p) {
    uint32_t a;
    asm("{ .reg .u64 t; cvta.to.shared.u64 t, %1; cvt.u32.u64 %0, t; }"
        : "=r"(a) : "l"(p));
    return a;
}
__device__ __forceinline__ void ldsm_x4(uint32_t r[4], uint32_t addr) {
    asm volatile("ldmatrix.sync.aligned.m8n8.x4.shared.b16 {%0,%1,%2,%3}, [%4];"
                 : "=r"(r[0]), "=r"(r[1]), "=r"(r[2]), "=r"(r[3]) : "r"(addr));
}
__device__ __forceinline__ void mma_bf16(float c[4],
                                         uint32_t a0, uint32_t a1, uint32_t a2, uint32_t a3,
                                         uint32_t b0, uint32_t b1) {
    asm volatile(
        "mma.sync.aligned.m16n8k16.row.col.f32.bf16.bf16.f32 "
        "{%0,%1,%2,%3}, {%4,%5,%6,%7}, {%8,%9}, {%0,%1,%2,%3};"
        : "+f"(c[0]), "+f"(c[1]), "+f"(c[2]), "+f"(c[3])
        : "r"(a0), "r"(a1), "r"(a2), "r"(a3), "r"(b0), "r"(b1));
}

// ---------------------------------------------------------------------------
// fp32 -> (bf16 hi, bf16 lo) conversion
// ---------------------------------------------------------------------------
__device__ __forceinline__ void split_bf16(float x, __nv_bfloat16& h, __nv_bfloat16& l) {
    h = __float2bfloat16(x);
    l = __float2bfloat16(x - __bfloat162float(h));
}

__global__ __launch_bounds__(256) void cvt_kernel(const float* __restrict__ src,
                                                  int n4, int sel)
{
    int i = blockIdx.x * blockDim.x + threadIdx.x;
    if (i >= n4) return;
    __nv_bfloat16* hp;
    __nv_bfloat16* lp;
    if (sel == 0)      { hp = g_in_h;   lp = g_in_l;  }
    else if (sel == 1) { hp = g_win_h;  lp = g_win_l; }
    else               { hp = g_wout_h; lp = g_wout_l; }
    float4 v = ((const float4*)src)[i];
    __nv_bfloat16 h0, h1, h2, h3, l0, l1, l2, l3;
    split_bf16(v.x, h0, l0); split_bf16(v.y, h1, l1);
    split_bf16(v.z, h2, l2); split_bf16(v.w, h3, l3);
    __nv_bfloat162 a, b;
    a.x = h0; a.y = h1; b.x = h2; b.y = h3;
    *(__nv_bfloat162*)(hp + 4 * (size_t)i)     = a;
    *(__nv_bfloat162*)(hp + 4 * (size_t)i + 2) = b;
    a.x = l0; a.y = l1; b.x = l2; b.y = l3;
    *(__nv_bfloat162*)(lp + 4 * (size_t)i)     = a;
    *(__nv_bfloat162*)(lp + 4 * (size_t)i + 2) = b;
}

// ---------------------------------------------------------------------------
// HMMA split-bf16 NT GEMM: C[m][n] = sum_k A[m][k]*B[n][k] (fp32 accum)
// D = Ah*Bh + Ah*Bl + Al*Bh  (Al*Bl dropped: ~2^-16 relative)
// BM=BN=128, BK=32, 256 threads (8 warps), warp tile 64x32 (2x4 warp grid).
// smem: K-major tiles, row stride 40 halves (pad 8) -> conflict-free ldmatrix.
// MODE 0: A=input(hi/lo), B=w_in(hi/lo), scatter fp32 into g_q/g_k/g_v
// MODE 1: A=ctx(hi/lo),   B=w_out(hi/lo), write fp32 Cout row-major
// ---------------------------------------------------------------------------
#define RS 40                          // smem row stride in halves
#define AH_OFF 0                       // offsets in halves
#define AL_OFF (128 * RS)
#define BH_OFF (2 * 128 * RS)
#define BL_OFF (3 * 128 * RS)
#define SM_HALVES (4 * 128 * RS)       // 20480 halves = 40960 B

template <int MODE>
__global__ __launch_bounds__(256, 1) void gemm_hmma(float* __restrict__ Cout)
{
    __shared__ __align__(16) __nv_bfloat16 smh[SM_HALVES];

    const int tid  = threadIdx.x;
    const int wid  = tid >> 5;
    const int lane = tid & 31;
    const int wy = wid >> 2;           // 0..1  (m)
    const int wx = wid & 3;            // 0..3  (n)
    const int g = lane >> 2;           // 0..7
    const int t = lane & 3;            // 0..3
    const int m0 = blockIdx.y * 128;
    const int n0 = blockIdx.x * 128;

    const __nv_bfloat16* __restrict__ Ah = (MODE == 0) ? g_in_h  : g_ctx_h;
    const __nv_bfloat16* __restrict__ Al = (MODE == 0) ? g_in_l  : g_ctx_l;
    const __nv_bfloat16* __restrict__ Bh = (MODE == 0) ? g_win_h : g_wout_h;
    const __nv_bfloat16* __restrict__ Bl = (MODE == 0) ? g_win_l : g_wout_l;

    float acc[4][4][4];
#pragma unroll
    for (int mi = 0; mi < 4; mi++)
#pragma unroll
        for (int nj = 0; nj < 4; nj++)
#pragma unroll
            for (int q = 0; q < 4; q++) acc[mi][nj][q] = 0.f;

    // ldmatrix lane->address components (row within 16, col half-offset)
    const int lrow = lane & 15;
    const int lcol = (lane >> 4) << 3;   // 0 or 8

    for (int k0 = 0; k0 < KDIM; k0 += 32) {
        // ---- global loads into regs (each thread: 2 chunk-slots per matrix)
        uint4 rah[2], ral[2], rbh[2], rbl[2];
#pragma unroll
        for (int i = 0; i < 2; i++) {
            const int s = i * 256 + tid;
            const int r = s >> 2, ck = s & 3;
            const size_t ga = (size_t)(m0 + r) * KDIM + k0 + ck * 8;
            const size_t gb = (size_t)(n0 + r) * KDIM + k0 + ck * 8;
            rah[i] = *(const uint4*)(Ah + ga);
            ral[i] = *(const uint4*)(Al + ga);
            rbh[i] = *(const uint4*)(Bh + gb);
            rbl[i] = *(const uint4*)(Bl + gb);
        }
        __syncthreads();   // previous iteration's readers done
#pragma unroll
        for (int i = 0; i < 2; i++) {
            const int s = i * 256 + tid;
            const int r = s >> 2, ck = s & 3;
            const int off = r * RS + ck * 8;
            *(uint4*)(smh + AH_OFF + off) = rah[i];
            *(uint4*)(smh + AL_OFF + off) = ral[i];
            *(uint4*)(smh + BH_OFF + off) = rbh[i];
            *(uint4*)(smh + BL_OFF + off) = rbl[i];
        }
        __syncthreads();

        // ---- compute 2 k-steps of 16
#pragma unroll
        for (int ks = 0; ks < 2; ks++) {
            const int kc = ks * 16 + lcol;

            uint32_t fah[4][4], fal[4][4];
#pragma unroll
            for (int mi = 0; mi < 4; mi++) {
                uint32_t ad = smem_u32(&smh[AH_OFF + (wy * 64 + mi * 16 + lrow) * RS + kc]);
                ldsm_x4(fah[mi], ad);
                ldsm_x4(fal[mi], ad + AL_OFF * 2);   // +halves*2 bytes
            }
            uint32_t fbh[2][4], fbl[2][4];
#pragma unroll
            for (int p = 0; p < 2; p++) {
                uint32_t bd = smem_u32(&smh[BH_OFF + (wx * 32 + p * 16 + lrow) * RS + kc]);
                ldsm_x4(fbh[p], bd);
                ldsm_x4(fbl[p], bd + (BL_OFF - BH_OFF) * 2);
            }
#pragma unroll
            for (int mi = 0; mi < 4; mi++)
#pragma unroll
                for (int nj = 0; nj < 4; nj++) {
                    const int p = nj >> 1, o = nj & 1;
                    mma_bf16(acc[mi][nj], fah[mi][0], fah[mi][1], fah[mi][2], fah[mi][3],
                             fbh[p][o], fbh[p][o + 2]);
                    mma_bf16(acc[mi][nj], fah[mi][0], fah[mi][1], fah[mi][2], fah[mi][3],
                             fbl[p][o], fbl[p][o + 2]);
                    mma_bf16(acc[mi][nj], fal[mi][0], fal[mi][1], fal[mi][2], fal[mi][3],
                             fbh[p][o], fbh[p][o + 2]);
                }
        }
    }

    // ---- epilogue
#pragma unroll
    for (int mi = 0; mi < 4; mi++) {
        const int row0 = m0 + wy * 64 + mi * 16 + g;
#pragma unroll
        for (int nj = 0; nj < 4; nj++) {
            const int col = n0 + wx * 32 + nj * 8 + 2 * t;
            float2 v0 = make_float2(acc[mi][nj][0], acc[mi][nj][1]);
            float2 v1 = make_float2(acc[mi][nj][2], acc[mi][nj][3]);
            if (MODE == 1) {
                *(float2*)&Cout[(size_t)row0 * CDIM + col]       = v0;
                *(float2*)&Cout[(size_t)(row0 + 8) * CDIM + col] = v1;
            } else {
                const int which = col >> 10;        // 0=q 1=k 2=v
                float* dst = (which == 0) ? g_q : ((which == 1) ? g_k : g_v);
                const int hh = (col & 1023) >> 6;
                const int dd = col & 63;
                const int b0r = row0 >> 11, l0r = row0 & 2047;
                float* p0 = dst + (((size_t)(b0r * NHEAD + hh)) * LSEQ + l0r) * DHEAD + dd;
                *(float2*)p0 = v0;
                const int r1 = row0 + 8;
                const int b1r = r1 >> 11, l1r = r1 & 2047;
                float* p1 = dst + (((size_t)(b1r * NHEAD + hh)) * LSEQ + l1r) * DHEAD + dd;
                *(float2*)p1 = v1;
            }
        }
    }
}

// ---------------------------------------------------------------------------
// Causal flash attention, fp32. Br=Bc=64, 256 threads, 4x4 per-thread tile.
// grid: (L/64, B*H). Writes ctx as bf16 hi/lo for the output projection.
// ---------------------------------------------------------------------------
#define SPAD 65
#define SMEM_ATTN (4 * 64 * SPAD * (int)sizeof(float))

__device__ __forceinline__ float warp16_max(float v) {
#pragma unroll
    for (int off = 8; off; off >>= 1)
        v = fmaxf(v, __shfl_xor_sync(0xffffffffu, v, off));
    return v;
}
__device__ __forceinline__ float warp16_sum(float v) {
#pragma unroll
    for (int off = 8; off; off >>= 1)
        v += __shfl_xor_sync(0xffffffffu, v, off);
    return v;
}

__global__ __launch_bounds__(256) void attn_kernel()
{
    extern __shared__ float sm[];
    float* Qs = sm;
    float* Ks = sm + 64 * SPAD;
    float* Vs = sm + 2 * 64 * SPAD;
    float* Ps = sm + 3 * 64 * SPAD;

    const int tid = threadIdx.x;
    const int tx = tid & 15;
    const int ty = tid >> 4;
    const int bh = blockIdx.y;
    const int qt = blockIdx.x;
    const int qbase = qt * 64;

    const float* __restrict__ Q = g_q + (size_t)bh * LSEQ * DHEAD;
    const float* __restrict__ K = g_k + (size_t)bh * LSEQ * DHEAD;
    const float* __restrict__ V = g_v + (size_t)bh * LSEQ * DHEAD;

    const int lr = tid >> 4;
    const int lc = (tid & 15) * 4;
#pragma unroll
    for (int r = 0; r < 4; r++) {
        float4 v4 = *(const float4*)&Q[(size_t)(qbase + lr + 16 * r) * DHEAD + lc];
        float* p = &Qs[(lr + 16 * r) * SPAD + lc];
        p[0] = v4.x; p[1] = v4.y; p[2] = v4.z; p[3] = v4.w;
    }

    float Ob[4][4];
    float mrow[4], lrow[4];
#pragma unroll
    for (int i = 0; i < 4; i++) {
        mrow[i] = -1e30f; lrow[i] = 0.f;
#pragma unroll
        for (int j = 0; j < 4; j++) Ob[i][j] = 0.f;
    }
    const float scale = 0.125f;

    const int ntiles = qt + 1;
    for (int tgt = 0; tgt < ntiles; tgt++) {
        const int kbase = tgt * 64;

        __syncthreads();
#pragma unroll
        for (int r = 0; r < 4; r++) {
            float4 kv = *(const float4*)&K[(size_t)(kbase + lr + 16 * r) * DHEAD + lc];
            float4 vv = *(const float4*)&V[(size_t)(kbase + lr + 16 * r) * DHEAD + lc];
            float* pk = &Ks[(lr + 16 * r) * SPAD + lc];
            float* pv = &Vs[(lr + 16 * r) * SPAD + lc];
            pk[0] = kv.x; pk[1] = kv.y; pk[2] = kv.z; pk[3] = kv.w;
            pv[0] = vv.x; pv[1] = vv.y; pv[2] = vv.z; pv[3] = vv.w;
        }
        __syncthreads();

        float S[4][4];
#pragma unroll
        for (int i = 0; i < 4; i++)
#pragma unroll
            for (int j = 0; j < 4; j++) S[i][j] = 0.f;

#pragma unroll 8
        for (int d = 0; d < 64; d++) {
            float qa[4], kb[4];
#pragma unroll
            for (int i = 0; i < 4; i++) qa[i] = Qs[(ty * 4 + i) * SPAD + d];
#pragma unroll
            for (int j = 0; j < 4; j++) kb[j] = Ks[(tx * 4 + j) * SPAD + d];
#pragma unroll
            for (int i = 0; i < 4; i++)
#pragma unroll
                for (int j = 0; j < 4; j++)
                    S[i][j] = fmaf(qa[i], kb[j], S[i][j]);
        }

        const bool diag = (tgt == qt);
#pragma unroll
        for (int i = 0; i < 4; i++)
#pragma unroll
            for (int j = 0; j < 4; j++) {
                S[i][j] *= scale;
                if (diag && (kbase + tx * 4 + j > qbase + ty * 4 + i))
                    S[i][j] = -1e30f;
            }

#pragma unroll
        for (int i = 0; i < 4; i++) {
            float rmax = fmaxf(fmaxf(S[i][0], S[i][1]), fmaxf(S[i][2], S[i][3]));
            rmax = warp16_max(rmax);
            const float mnew = fmaxf(mrow[i], rmax);
            const float alpha = __expf(mrow[i] - mnew);
            float rs = 0.f;
#pragma unroll
            for (int j = 0; j < 4; j++) {
                S[i][j] = __expf(S[i][j] - mnew);
                rs += S[i][j];
            }
            rs = warp16_sum(rs);
            lrow[i] = lrow[i] * alpha + rs;
            mrow[i] = mnew;
#pragma unroll
            for (int j = 0; j < 4; j++) {
                Ob[i][j] *= alpha;
                Ps[(ty * 4 + i) * SPAD + tx * 4 + j] = S[i][j];
            }
        }
        __syncthreads();

#pragma unroll 8
        for (int n = 0; n < 64; n++) {
            float pa[4], vb[4];
#pragma unroll
            for (int i = 0; i < 4; i++) pa[i] = Ps[(ty * 4 + i) * SPAD + n];
#pragma unroll
            for (int j = 0; j < 4; j++) vb[j] = Vs[n * SPAD + tx * 4 + j];
#pragma unroll
            for (int i = 0; i < 4; i++)
#pragma unroll
                for (int j = 0; j < 4; j++)
                    Ob[i][j] = fmaf(pa[i], vb[j], Ob[i][j]);
        }
    }

    // finalize + write ctx hi/lo bf16 [b*l][h*64+d]
    const int b = bh >> 4;
    const int h = bh & 15;
#pragma unroll
    for (int i = 0; i < 4; i++) {
        const float inv = 1.f / lrow[i];
        const int row = qbase + ty * 4 + i;
        const size_t base = ((size_t)(b * LSEQ + row)) * CDIM + h * DHEAD + tx * 4;
        float o0 = Ob[i][0] * inv, o1 = Ob[i][1] * inv;
        float o2 = Ob[i][2] * inv, o3 = Ob[i][3] * inv;
        __nv_bfloat16 h0, h1, h2, h3, l0, l1, l2, l3;
        split_bf16(o0, h0, l0); split_bf16(o1, h1, l1);
        split_bf16(o2, h2, l2); split_bf16(o3, h3, l3);
        __nv_bfloat162 a, bb2;
        a.x = h0; a.y = h1; bb2.x = h2; bb2.y = h3;
        *(__nv_bfloat162*)(g_ctx_h + base)     = a;
        *(__nv_bfloat162*)(g_ctx_h + base + 2) = bb2;
        a.x = l0; a.y = l1; bb2.x = l2; bb2.y = l3;
        *(__nv_bfloat162*)(g_ctx_l + base)     = a;
        *(__nv_bfloat162*)(g_ctx_l + base + 2) = bb2;
    }
}

// ---------------------------------------------------------------------------
extern "C" void kernel_launch(void* const* d_in, const int* in_sizes, int n_in,
                              void* d_out, int out_size)
{
    const float* input = (const float*)d_in[0];  // [4,2048,1024]
    const float* w_in  = (const float*)d_in[1];  // [3072,1024]
    const float* w_out = (const float*)d_in[2];  // [1024,1024]
    float* out = (float*)d_out;                  // [8192,1024]

    cudaFuncSetAttribute(attn_kernel,
                         cudaFuncAttributeMaxDynamicSharedMemorySize, SMEM_ATTN);

    // 0) fp32 -> bf16 hi/lo conversions
    cvt_kernel<<<(MROWS * KDIM / 4) / 256, 256>>>(input, MROWS * KDIM / 4, 0);
    cvt_kernel<<<(3 * CDIM * KDIM / 4) / 256, 256>>>(w_in, 3 * CDIM * KDIM / 4, 1);
    cvt_kernel<<<(CDIM * KDIM / 4) / 256, 256>>>(w_out, CDIM * KDIM / 4, 2);

    // 1) QKV projection (HMMA split-bf16), scatter into [b][h][l][d] fp32
    gemm_hmma<0><<<dim3(3 * CDIM / 128, MROWS / 128), 256>>>(nullptr);

    // 2) causal flash attention (fp32) -> ctx hi/lo
    attn_kernel<<<dim3(LSEQ / 64, BATCH * NHEAD), 256, SMEM_ATTN>>>();

    // 3) output projection (HMMA split-bf16)
    gemm_hmma<1><<<dim3(CDIM / 128, MROWS / 128), 256>>>(out);
}

// round 4
// speedup vs baseline: 2.2147x; 1.6522x over previous
#include <cuda_runtime.h>
#include <cuda_bf16.h>
#include <cstdint>

// ---------------------------------------------------------------------------
// Problem constants
// ---------------------------------------------------------------------------
#define BATCH 4
#define LSEQ  2048
#define CDIM  1024
#define NHEAD 16
#define DHEAD 64
#define MROWS (BATCH * LSEQ)   // 8192
#define KDIM  1024

// ---------------------------------------------------------------------------
// Device-global scratch (allocation-free per harness rules)
// ---------------------------------------------------------------------------
__device__ __nv_bfloat16 g_in_h [MROWS * KDIM];
__device__ __nv_bfloat16 g_in_l [MROWS * KDIM];
__device__ __nv_bfloat16 g_win_h[3 * CDIM * KDIM];
__device__ __nv_bfloat16 g_win_l[3 * CDIM * KDIM];
__device__ __nv_bfloat16 g_wout_h[CDIM * KDIM];
__device__ __nv_bfloat16 g_wout_l[CDIM * KDIM];
// q/k/v as bf16 hi/lo, [b][h][l][d]
__device__ __nv_bfloat16 g_qh[BATCH * NHEAD * LSEQ * DHEAD];
__device__ __nv_bfloat16 g_ql[BATCH * NHEAD * LSEQ * DHEAD];
__device__ __nv_bfloat16 g_kh[BATCH * NHEAD * LSEQ * DHEAD];
__device__ __nv_bfloat16 g_kl[BATCH * NHEAD * LSEQ * DHEAD];
__device__ __nv_bfloat16 g_vh[BATCH * NHEAD * LSEQ * DHEAD];
__device__ __nv_bfloat16 g_vl[BATCH * NHEAD * LSEQ * DHEAD];
__device__ __nv_bfloat16 g_ctx_h[MROWS * CDIM];
__device__ __nv_bfloat16 g_ctx_l[MROWS * CDIM];

// ---------------------------------------------------------------------------
// Baseline-PTX tensor helpers (compute_103-safe: mma.sync + ldmatrix only)
// ---------------------------------------------------------------------------
__device__ __forceinline__ uint32_t smem_u32(const void* p) {
    uint32_t a;
    asm("{ .reg .u64 t; cvta.to.shared.u64 t, %1; cvt.u32.u64 %0, t; }"
        : "=r"(a) : "l"(p));
    return a;
}
__device__ __forceinline__ void ldsm_x4(uint32_t r[4], uint32_t addr) {
    asm volatile("ldmatrix.sync.aligned.m8n8.x4.shared.b16 {%0,%1,%2,%3}, [%4];"
                 : "=r"(r[0]), "=r"(r[1]), "=r"(r[2]), "=r"(r[3]) : "r"(addr));
}
__device__ __forceinline__ void ldsm_x4_t(uint32_t r[4], uint32_t addr) {
    asm volatile("ldmatrix.sync.aligned.m8n8.x4.trans.shared.b16 {%0,%1,%2,%3}, [%4];"
                 : "=r"(r[0]), "=r"(r[1]), "=r"(r[2]), "=r"(r[3]) : "r"(addr));
}
__device__ __forceinline__ void mma_bf16(float c[4],
                                         uint32_t a0, uint32_t a1, uint32_t a2, uint32_t a3,
                                         uint32_t b0, uint32_t b1) {
    asm volatile(
        "mma.sync.aligned.m16n8k16.row.col.f32.bf16.bf16.f32 "
        "{%0,%1,%2,%3}, {%4,%5,%6,%7}, {%8,%9}, {%0,%1,%2,%3};"
        : "+f"(c[0]), "+f"(c[1]), "+f"(c[2]), "+f"(c[3])
        : "r"(a0), "r"(a1), "r"(a2), "r"(a3), "r"(b0), "r"(b1));
}

__device__ __forceinline__ void split_bf16(float x, __nv_bfloat16& h, __nv_bfloat16& l) {
    h = __float2bfloat16(x);
    l = __float2bfloat16(x - __bfloat162float(h));
}
// pack (x,y) into bf16x2 hi and residual lo
__device__ __forceinline__ void pack_split2(float x, float y, uint32_t& hi, uint32_t& lo) {
    __nv_bfloat162 h = __floats2bfloat162_rn(x, y);
    float2 hf = __bfloat1622float2(h);
    __nv_bfloat162 l = __floats2bfloat162_rn(x - hf.x, y - hf.y);
    hi = *(uint32_t*)&h;
    lo = *(uint32_t*)&l;
}

// ---------------------------------------------------------------------------
// fp32 -> (bf16 hi, bf16 lo) conversion for the three fp32 inputs
// ---------------------------------------------------------------------------
__global__ __launch_bounds__(256) void cvt_kernel(const float* __restrict__ src,
                                                  int n4, int sel)
{
    int i = blockIdx.x * blockDim.x + threadIdx.x;
    if (i >= n4) return;
    __nv_bfloat16* hp;
    __nv_bfloat16* lp;
    if (sel == 0)      { hp = g_in_h;   lp = g_in_l;  }
    else if (sel == 1) { hp = g_win_h;  lp = g_win_l; }
    else               { hp = g_wout_h; lp = g_wout_l; }
    float4 v = ((const float4*)src)[i];
    __nv_bfloat16 h0, h1, h2, h3, l0, l1, l2, l3;
    split_bf16(v.x, h0, l0); split_bf16(v.y, h1, l1);
    split_bf16(v.z, h2, l2); split_bf16(v.w, h3, l3);
    __nv_bfloat162 a, b;
    a.x = h0; a.y = h1; b.x = h2; b.y = h3;
    *(__nv_bfloat162*)(hp + 4 * (size_t)i)     = a;
    *(__nv_bfloat162*)(hp + 4 * (size_t)i + 2) = b;
    a.x = l0; a.y = l1; b.x = l2; b.y = l3;
    *(__nv_bfloat162*)(lp + 4 * (size_t)i)     = a;
    *(__nv_bfloat162*)(lp + 4 * (size_t)i + 2) = b;
}

// ---------------------------------------------------------------------------
// HMMA split-bf16 NT GEMM: C[m][n] = sum_k A[m][k]*B[n][k] (fp32 accum)
// BM=BN=128, BK=32, 256 threads (8 warps), warp tile 64x32 (2x4 warp grid).
// MODE 0: A=input(hi/lo), B=w_in(hi/lo) -> q/k/v bf16 hi/lo [b][h][l][d]
// MODE 1: A=ctx(hi/lo),   B=w_out(hi/lo) -> fp32 Cout row-major
// ---------------------------------------------------------------------------
#define RS 40                          // gemm smem row stride in halves
#define AH_OFF 0
#define AL_OFF (128 * RS)
#define BH_OFF (2 * 128 * RS)
#define BL_OFF (3 * 128 * RS)
#define SM_HALVES (4 * 128 * RS)

template <int MODE>
__global__ __launch_bounds__(256, 1) void gemm_hmma(float* __restrict__ Cout)
{
    __shared__ __align__(16) __nv_bfloat16 smh[SM_HALVES];

    const int tid  = threadIdx.x;
    const int wid  = tid >> 5;
    const int lane = tid & 31;
    const int wy = wid >> 2;
    const int wx = wid & 3;
    const int g = lane >> 2;
    const int t = lane & 3;
    const int m0 = blockIdx.y * 128;
    const int n0 = blockIdx.x * 128;

    const __nv_bfloat16* __restrict__ Ah = (MODE == 0) ? g_in_h  : g_ctx_h;
    const __nv_bfloat16* __restrict__ Al = (MODE == 0) ? g_in_l  : g_ctx_l;
    const __nv_bfloat16* __restrict__ Bh = (MODE == 0) ? g_win_h : g_wout_h;
    const __nv_bfloat16* __restrict__ Bl = (MODE == 0) ? g_win_l : g_wout_l;

    float acc[4][4][4];
#pragma unroll
    for (int mi = 0; mi < 4; mi++)
#pragma unroll
        for (int nj = 0; nj < 4; nj++)
#pragma unroll
            for (int q = 0; q < 4; q++) acc[mi][nj][q] = 0.f;

    const int lrow = lane & 15;
    const int lcol = (lane >> 4) << 3;

    for (int k0 = 0; k0 < KDIM; k0 += 32) {
        uint4 rah[2], ral[2], rbh[2], rbl[2];
#pragma unroll
        for (int i = 0; i < 2; i++) {
            const int s = i * 256 + tid;
            const int r = s >> 2, ck = s & 3;
            const size_t ga = (size_t)(m0 + r) * KDIM + k0 + ck * 8;
            const size_t gb = (size_t)(n0 + r) * KDIM + k0 + ck * 8;
            rah[i] = *(const uint4*)(Ah + ga);
            ral[i] = *(const uint4*)(Al + ga);
            rbh[i] = *(const uint4*)(Bh + gb);
            rbl[i] = *(const uint4*)(Bl + gb);
        }
        __syncthreads();
#pragma unroll
        for (int i = 0; i < 2; i++) {
            const int s = i * 256 + tid;
            const int r = s >> 2, ck = s & 3;
            const int off = r * RS + ck * 8;
            *(uint4*)(smh + AH_OFF + off) = rah[i];
            *(uint4*)(smh + AL_OFF + off) = ral[i];
            *(uint4*)(smh + BH_OFF + off) = rbh[i];
            *(uint4*)(smh + BL_OFF + off) = rbl[i];
        }
        __syncthreads();

#pragma unroll
        for (int ks = 0; ks < 2; ks++) {
            const int kc = ks * 16 + lcol;
            uint32_t fah[4][4], fal[4][4];
#pragma unroll
            for (int mi = 0; mi < 4; mi++) {
                uint32_t ad = smem_u32(&smh[AH_OFF + (wy * 64 + mi * 16 + lrow) * RS + kc]);
                ldsm_x4(fah[mi], ad);
                ldsm_x4(fal[mi], ad + AL_OFF * 2);
            }
            uint32_t fbh[2][4], fbl[2][4];
#pragma unroll
            for (int p = 0; p < 2; p++) {
                uint32_t bd = smem_u32(&smh[BH_OFF + (wx * 32 + p * 16 + lrow) * RS + kc]);
                ldsm_x4(fbh[p], bd);
                ldsm_x4(fbl[p], bd + (BL_OFF - BH_OFF) * 2);
            }
#pragma unroll
            for (int mi = 0; mi < 4; mi++)
#pragma unroll
                for (int nj = 0; nj < 4; nj++) {
                    const int p = nj >> 1, o = nj & 1;
                    mma_bf16(acc[mi][nj], fah[mi][0], fah[mi][1], fah[mi][2], fah[mi][3],
                             fbh[p][o], fbh[p][o + 2]);
                    mma_bf16(acc[mi][nj], fah[mi][0], fah[mi][1], fah[mi][2], fah[mi][3],
                             fbl[p][o], fbl[p][o + 2]);
                    mma_bf16(acc[mi][nj], fal[mi][0], fal[mi][1], fal[mi][2], fal[mi][3],
                             fbh[p][o], fbh[p][o + 2]);
                }
        }
    }

    // ---- epilogue
#pragma unroll
    for (int mi = 0; mi < 4; mi++) {
        const int row0 = m0 + wy * 64 + mi * 16 + g;
        const int row1 = row0 + 8;
#pragma unroll
        for (int nj = 0; nj < 4; nj++) {
            const int col = n0 + wx * 32 + nj * 8 + 2 * t;
            if (MODE == 1) {
                *(float2*)&Cout[(size_t)row0 * CDIM + col] =
                    make_float2(acc[mi][nj][0], acc[mi][nj][1]);
                *(float2*)&Cout[(size_t)row1 * CDIM + col] =
                    make_float2(acc[mi][nj][2], acc[mi][nj][3]);
            } else {
                const int which = col >> 10;        // 0=q 1=k 2=v
                __nv_bfloat16* dh = (which == 0) ? g_qh : ((which == 1) ? g_kh : g_vh);
                __nv_bfloat16* dl = (which == 0) ? g_ql : ((which == 1) ? g_kl : g_vl);
                const int hh = (col & 1023) >> 6;
                const int dd = col & 63;
                uint32_t hi, lo;
                pack_split2(acc[mi][nj][0], acc[mi][nj][1], hi, lo);
                {
                    const int br = row0 >> 11, lr2 = row0 & 2047;
                    const size_t idx = (((size_t)(br * NHEAD + hh)) * LSEQ + lr2) * DHEAD + dd;
                    *(uint32_t*)(dh + idx) = hi;
                    *(uint32_t*)(dl + idx) = lo;
                }
                pack_split2(acc[mi][nj][2], acc[mi][nj][3], hi, lo);
                {
                    const int br = row1 >> 11, lr2 = row1 & 2047;
                    const size_t idx = (((size_t)(br * NHEAD + hh)) * LSEQ + lr2) * DHEAD + dd;
                    *(uint32_t*)(dh + idx) = hi;
                    *(uint32_t*)(dl + idx) = lo;
                }
            }
        }
    }
}

// ---------------------------------------------------------------------------
// HMMA causal flash attention, split-bf16, fp32 softmax/accum.
// Br=128, Bc=64, 256 threads (8 warps); warp w owns rows w*16..w*16+15.
// grid: (B*H, L/128), qtile reversed (heavy first).
// ---------------------------------------------------------------------------
#define ARS 72                              // attn smem row stride (halves)
#define QH_O 0
#define QL_O (128 * ARS)
#define KH_O (2 * 128 * ARS)
#define KL_O (KH_O + 64 * ARS)
#define VH_O (KH_O + 2 * 64 * ARS)
#define VL_O (KH_O + 3 * 64 * ARS)
#define ATTN_HALVES (2 * 128 * ARS + 4 * 64 * ARS)
#define SMEM_ATTN (ATTN_HALVES * 2)

__global__ __launch_bounds__(256, 1) void attn_hmma()
{
    extern __shared__ __align__(16) __nv_bfloat16 sh[];

    const int tid  = threadIdx.x;
    const int w    = tid >> 5;
    const int lane = tid & 31;
    const int g = lane >> 2;
    const int t = lane & 3;
    const int lrow = lane & 15;
    const int lcol = (lane >> 4) << 3;

    const int bh = blockIdx.x;
    const int qt = (int)gridDim.y - 1 - (int)blockIdx.y;   // heavy tiles first
    const int qbase = qt * 128;

    const size_t hoff = (size_t)bh * LSEQ * DHEAD;
    const __nv_bfloat16* __restrict__ Qh = g_qh + hoff;
    const __nv_bfloat16* __restrict__ Ql = g_ql + hoff;
    const __nv_bfloat16* __restrict__ Kh = g_kh + hoff;
    const __nv_bfloat16* __restrict__ Kl = g_kl + hoff;
    const __nv_bfloat16* __restrict__ Vh = g_vh + hoff;
    const __nv_bfloat16* __restrict__ Vl = g_vl + hoff;

    // ---- load Q tile (128x64 hi/lo) into smem
#pragma unroll
    for (int it = 0; it < 4; it++) {
        const int s = it * 256 + tid;
        const int r = s >> 3, ck = s & 7;
        const size_t go = (size_t)(qbase + r) * DHEAD + ck * 8;
        const int so = r * ARS + ck * 8;
        *(uint4*)(sh + QH_O + so) = *(const uint4*)(Qh + go);
        *(uint4*)(sh + QL_O + so) = *(const uint4*)(Ql + go);
    }
    __syncthreads();

    // ---- Q fragments resident in registers
    uint32_t qfh[4][4], qfl[4][4];
#pragma unroll
    for (int ks = 0; ks < 4; ks++) {
        uint32_t ad = smem_u32(&sh[QH_O + (w * 16 + lrow) * ARS + ks * 16 + lcol]);
        ldsm_x4(qfh[ks], ad);
        ldsm_x4(qfl[ks], ad + (QL_O - QH_O) * 2);
    }

    float O[8][4];
#pragma unroll
    for (int j = 0; j < 8; j++)
#pragma unroll
        for (int q = 0; q < 4; q++) O[j][q] = 0.f;
    float m0 = -1e30f, m1 = -1e30f, l0 = 0.f, l1 = 0.f;
    const float scale = 0.125f;
    const int row0 = qbase + w * 16 + g;
    const int row1 = row0 + 8;

    const int nkt = 2 * qt + 2;
    for (int kt = 0; kt < nkt; kt++) {
        const int kbase = kt * 64;

        __syncthreads();   // previous iteration's smem readers done
#pragma unroll
        for (int it = 0; it < 2; it++) {
            const int s = it * 256 + tid;
            const int r = s >> 3, ck = s & 7;
            const size_t go = (size_t)(kbase + r) * DHEAD + ck * 8;
            const int so = r * ARS + ck * 8;
            *(uint4*)(sh + KH_O + so) = *(const uint4*)(Kh + go);
            *(uint4*)(sh + KL_O + so) = *(const uint4*)(Kl + go);
            *(uint4*)(sh + VH_O + so) = *(const uint4*)(Vh + go);
            *(uint4*)(sh + VL_O + so) = *(const uint4*)(Vl + go);
        }
        __syncthreads();

        // ---- S = Q K^T (3-term split), fp32 accum
        float S[8][4];
#pragma unroll
        for (int j = 0; j < 8; j++)
#pragma unroll
            for (int q = 0; q < 4; q++) S[j][q] = 0.f;

#pragma unroll
        for (int ks = 0; ks < 4; ks++) {
#pragma unroll
            for (int p = 0; p < 4; p++) {
                uint32_t kh0[4], kl0[4];
                uint32_t bd = smem_u32(&sh[KH_O + (p * 16 + lrow) * ARS + ks * 16 + lcol]);
                ldsm_x4(kh0, bd);
                ldsm_x4(kl0, bd + (KL_O - KH_O) * 2);
#pragma unroll
                for (int o = 0; o < 2; o++) {
                    const int j = 2 * p + o;
                    mma_bf16(S[j], qfh[ks][0], qfh[ks][1], qfh[ks][2], qfh[ks][3],
                             kh0[o], kh0[o + 2]);
                    mma_bf16(S[j], qfh[ks][0], qfh[ks][1], qfh[ks][2], qfh[ks][3],
                             kl0[o], kl0[o + 2]);
                    mma_bf16(S[j], qfl[ks][0], qfl[ks][1], qfl[ks][2], qfl[ks][3],
                             kh0[o], kh0[o + 2]);
                }
            }
        }

        // ---- causal mask on diagonal-overlapping tiles
        if (kt >= nkt - 2) {
#pragma unroll
            for (int j = 0; j < 8; j++) {
                const int col = kbase + j * 8 + 2 * t;
                if (col > row0)     S[j][0] = -1e30f;
                if (col + 1 > row0) S[j][1] = -1e30f;
                if (col > row1)     S[j][2] = -1e30f;
                if (col + 1 > row1) S[j][3] = -1e30f;
            }
        }

        // ---- online softmax (fp32)
        float mt0 = -1e30f, mt1 = -1e30f;
#pragma unroll
        for (int j = 0; j < 8; j++) {
            mt0 = fmaxf(mt0, fmaxf(S[j][0], S[j][1]));
            mt1 = fmaxf(mt1, fmaxf(S[j][2], S[j][3]));
        }
        mt0 = fmaxf(mt0, __shfl_xor_sync(0xffffffffu, mt0, 1));
        mt0 = fmaxf(mt0, __shfl_xor_sync(0xffffffffu, mt0, 2));
        mt1 = fmaxf(mt1, __shfl_xor_sync(0xffffffffu, mt1, 1));
        mt1 = fmaxf(mt1, __shfl_xor_sync(0xffffffffu, mt1, 2));
        const float mn0 = fmaxf(m0, mt0 * scale);
        const float mn1 = fmaxf(m1, mt1 * scale);
        const float a0 = __expf(m0 - mn0);
        const float a1 = __expf(m1 - mn1);
        m0 = mn0; m1 = mn1;

        float rs0 = 0.f, rs1 = 0.f;
#pragma unroll
        for (int j = 0; j < 8; j++) {
            S[j][0] = __expf(fmaf(S[j][0], scale, -mn0));
            S[j][1] = __expf(fmaf(S[j][1], scale, -mn0));
            S[j][2] = __expf(fmaf(S[j][2], scale, -mn1));
            S[j][3] = __expf(fmaf(S[j][3], scale, -mn1));
            rs0 += S[j][0] + S[j][1];
            rs1 += S[j][2] + S[j][3];
        }
        rs0 += __shfl_xor_sync(0xffffffffu, rs0, 1);
        rs0 += __shfl_xor_sync(0xffffffffu, rs0, 2);
        rs1 += __shfl_xor_sync(0xffffffffu, rs1, 1);
        rs1 += __shfl_xor_sync(0xffffffffu, rs1, 2);
        l0 = l0 * a0 + rs0;
        l1 = l1 * a1 + rs1;
#pragma unroll
        for (int j = 0; j < 8; j++) {
            O[j][0] *= a0; O[j][1] *= a0;
            O[j][2] *= a1; O[j][3] *= a1;
        }

        // ---- O += P V (3-term split); P fragments straight from S regs
#pragma unroll
        for (int jj = 0; jj < 4; jj++) {
            uint32_t ah[4], al[4];
            pack_split2(S[2 * jj][0],     S[2 * jj][1],     ah[0], al[0]);
            pack_split2(S[2 * jj][2],     S[2 * jj][3],     ah[1], al[1]);
            pack_split2(S[2 * jj + 1][0], S[2 * jj + 1][1], ah[2], al[2]);
            pack_split2(S[2 * jj + 1][2], S[2 * jj + 1][3], ah[3], al[3]);
#pragma unroll
            for (int p = 0; p < 4; p++) {
                uint32_t vh0[4], vl0[4];
                uint32_t vd = smem_u32(&sh[VH_O + (jj * 16 + lrow) * ARS + p * 16 + lcol]);
                ldsm_x4_t(vh0, vd);
                ldsm_x4_t(vl0, vd + (VL_O - VH_O) * 2);
#pragma unroll
                for (int o = 0; o < 2; o++) {
                    const int j2 = 2 * p + o;
                    mma_bf16(O[j2], ah[0], ah[1], ah[2], ah[3], vh0[2 * o], vh0[2 * o + 1]);
                    mma_bf16(O[j2], ah[0], ah[1], ah[2], ah[3], vl0[2 * o], vl0[2 * o + 1]);
                    mma_bf16(O[j2], al[0], al[1], al[2], al[3], vh0[2 * o], vh0[2 * o + 1]);
                }
            }
        }
    }

    // ---- finalize: O /= l, write ctx hi/lo bf16 [b*l][h*64+d]
    const int b = bh >> 4;
    const int h = bh & 15;
    const float i0 = 1.f / l0;
    const float i1 = 1.f / l1;
#pragma unroll
    for (int j = 0; j < 8; j++) {
        const int col = h * DHEAD + j * 8 + 2 * t;
        uint32_t hi, lo;
        pack_split2(O[j][0] * i0, O[j][1] * i0, hi, lo);
        {
            const size_t idx = ((size_t)(b * LSEQ + row0)) * CDIM + col;
            *(uint32_t*)(g_ctx_h + idx) = hi;
            *(uint32_t*)(g_ctx_l + idx) = lo;
        }
        pack_split2(O[j][2] * i1, O[j][3] * i1, hi, lo);
        {
            const size_t idx = ((size_t)(b * LSEQ + row1)) * CDIM + col;
            *(uint32_t*)(g_ctx_h + idx) = hi;
            *(uint32_t*)(g_ctx_l + idx) = lo;
        }
    }
}

// ---------------------------------------------------------------------------
extern "C" void kernel_launch(void* const* d_in, const int* in_sizes, int n_in,
                              void* d_out, int out_size)
{
    const float* input = (const float*)d_in[0];  // [4,2048,1024]
    const float* w_in  = (const float*)d_in[1];  // [3072,1024]
    const float* w_out = (const float*)d_in[2];  // [1024,1024]
    float* out = (float*)d_out;                  // [8192,1024]

    cudaFuncSetAttribute(attn_hmma,
                         cudaFuncAttributeMaxDynamicSharedMemorySize, SMEM_ATTN);

    // 0) fp32 -> bf16 hi/lo conversions
    cvt_kernel<<<(MROWS * KDIM / 4) / 256, 256>>>(input, MROWS * KDIM / 4, 0);
    cvt_kernel<<<(3 * CDIM * KDIM / 4) / 256, 256>>>(w_in, 3 * CDIM * KDIM / 4, 1);
    cvt_kernel<<<(CDIM * KDIM / 4) / 256, 256>>>(w_out, CDIM * KDIM / 4, 2);

    // 1) QKV projection (HMMA split-bf16) -> q/k/v bf16 hi/lo [b][h][l][d]
    gemm_hmma<0><<<dim3(3 * CDIM / 128, MROWS / 128), 256>>>(nullptr);

    // 2) causal flash attention (HMMA split-bf16) -> ctx hi/lo
    attn_hmma<<<dim3(BATCH * NHEAD, LSEQ / 128), 256, SMEM_ATTN>>>();

    // 3) output projection (HMMA split-bf16)
    gemm_hmma<1><<<dim3(CDIM / 128, MROWS / 128), 256>>>(out);
}

// round 5
// speedup vs baseline: 2.5662x; 1.1587x over previous
#include <cuda_runtime.h>
#include <cuda_bf16.h>
#include <cstdint>

// ---------------------------------------------------------------------------
// Problem constants
// ---------------------------------------------------------------------------
#define BATCH 4
#define LSEQ  2048
#define CDIM  1024
#define NHEAD 16
#define DHEAD 64
#define MROWS (BATCH * LSEQ)   // 8192
#define KDIM  1024

// ---------------------------------------------------------------------------
// Device-global scratch (allocation-free per harness rules)
// ---------------------------------------------------------------------------
__device__ __nv_bfloat16 g_in_h [MROWS * KDIM];
__device__ __nv_bfloat16 g_in_l [MROWS * KDIM];
__device__ __nv_bfloat16 g_win_h[3 * CDIM * KDIM];
__device__ __nv_bfloat16 g_win_l[3 * CDIM * KDIM];
__device__ __nv_bfloat16 g_wout_h[CDIM * KDIM];
__device__ __nv_bfloat16 g_wout_l[CDIM * KDIM];
__device__ __nv_bfloat16 g_qh[BATCH * NHEAD * LSEQ * DHEAD];
__device__ __nv_bfloat16 g_ql[BATCH * NHEAD * LSEQ * DHEAD];
__device__ __nv_bfloat16 g_kh[BATCH * NHEAD * LSEQ * DHEAD];
__device__ __nv_bfloat16 g_kl[BATCH * NHEAD * LSEQ * DHEAD];
__device__ __nv_bfloat16 g_vh[BATCH * NHEAD * LSEQ * DHEAD];
__device__ __nv_bfloat16 g_vl[BATCH * NHEAD * LSEQ * DHEAD];
__device__ __nv_bfloat16 g_ctx_h[MROWS * CDIM];
__device__ __nv_bfloat16 g_ctx_l[MROWS * CDIM];

// ---------------------------------------------------------------------------
// Baseline-PTX helpers (compute_103-safe: mma.sync, ldmatrix, cp.async)
// ---------------------------------------------------------------------------
__device__ __forceinline__ uint32_t smem_u32(const void* p) {
    uint32_t a;
    asm("{ .reg .u64 t; cvta.to.shared.u64 t, %1; cvt.u32.u64 %0, t; }"
        : "=r"(a) : "l"(p));
    return a;
}
__device__ __forceinline__ void ldsm_x4(uint32_t r[4], uint32_t addr) {
    asm volatile("ldmatrix.sync.aligned.m8n8.x4.shared.b16 {%0,%1,%2,%3}, [%4];"
                 : "=r"(r[0]), "=r"(r[1]), "=r"(r[2]), "=r"(r[3]) : "r"(addr));
}
__device__ __forceinline__ void ldsm_x4_t(uint32_t r[4], uint32_t addr) {
    asm volatile("ldmatrix.sync.aligned.m8n8.x4.trans.shared.b16 {%0,%1,%2,%3}, [%4];"
                 : "=r"(r[0]), "=r"(r[1]), "=r"(r[2]), "=r"(r[3]) : "r"(addr));
}
__device__ __forceinline__ void mma_bf16(float c[4],
                                         uint32_t a0, uint32_t a1, uint32_t a2, uint32_t a3,
                                         uint32_t b0, uint32_t b1) {
    asm volatile(
        "mma.sync.aligned.m16n8k16.row.col.f32.bf16.bf16.f32 "
        "{%0,%1,%2,%3}, {%4,%5,%6,%7}, {%8,%9}, {%0,%1,%2,%3};"
        : "+f"(c[0]), "+f"(c[1]), "+f"(c[2]), "+f"(c[3])
        : "r"(a0), "r"(a1), "r"(a2), "r"(a3), "r"(b0), "r"(b1));
}
__device__ __forceinline__ void cp16(uint32_t dst, const void* src) {
    asm volatile("cp.async.cg.shared.global [%0], [%1], 16;" :: "r"(dst), "l"(src));
}
#define CP_COMMIT() asm volatile("cp.async.commit_group;" ::: "memory")
#define CP_WAIT(N)  asm volatile("cp.async.wait_group %0;" :: "n"(N) : "memory")

__device__ __forceinline__ void split_bf16(float x, __nv_bfloat16& h, __nv_bfloat16& l) {
    h = __float2bfloat16(x);
    l = __float2bfloat16(x - __bfloat162float(h));
}
__device__ __forceinline__ void pack_split2(float x, float y, uint32_t& hi, uint32_t& lo) {
    __nv_bfloat162 h = __floats2bfloat162_rn(x, y);
    float2 hf = __bfloat1622float2(h);
    __nv_bfloat162 l = __floats2bfloat162_rn(x - hf.x, y - hf.y);
    hi = *(uint32_t*)&h;
    lo = *(uint32_t*)&l;
}

// ---------------------------------------------------------------------------
// fp32 -> (bf16 hi, bf16 lo) conversion
// ---------------------------------------------------------------------------
__global__ __launch_bounds__(256) void cvt_kernel(const float* __restrict__ src,
                                                  int n4, int sel)
{
    int i = blockIdx.x * blockDim.x + threadIdx.x;
    if (i >= n4) return;
    __nv_bfloat16* hp;
    __nv_bfloat16* lp;
    if (sel == 0)      { hp = g_in_h;   lp = g_in_l;  }
    else if (sel == 1) { hp = g_win_h;  lp = g_win_l; }
    else               { hp = g_wout_h; lp = g_wout_l; }
    float4 v = ((const float4*)src)[i];
    __nv_bfloat16 h0, h1, h2, h3, l0, l1, l2, l3;
    split_bf16(v.x, h0, l0); split_bf16(v.y, h1, l1);
    split_bf16(v.z, h2, l2); split_bf16(v.w, h3, l3);
    __nv_bfloat162 a, b;
    a.x = h0; a.y = h1; b.x = h2; b.y = h3;
    *(__nv_bfloat162*)(hp + 4 * (size_t)i)     = a;
    *(__nv_bfloat162*)(hp + 4 * (size_t)i + 2) = b;
    a.x = l0; a.y = l1; b.x = l2; b.y = l3;
    *(__nv_bfloat162*)(lp + 4 * (size_t)i)     = a;
    *(__nv_bfloat162*)(lp + 4 * (size_t)i + 2) = b;
}

// ---------------------------------------------------------------------------
// HMMA split-bf16 NT GEMM with 3-stage cp.async pipeline.
// BM=BN=128, BK=32, 256 threads (8 warps), warp tile 64x32.
// Stage layout (bytes): AH 0, AL 10240, BH 20480, BL 30720; stage = 40960.
// ---------------------------------------------------------------------------
#define RS 40                             // row stride in halves (80 B)
#define G_AL 10240
#define G_BH 20480
#define G_BL 30720
#define G_STAGE 40960
#define SMEM_GEMM (3 * G_STAGE)           // 122880

template <int MODE>
__global__ __launch_bounds__(256, 1) void gemm_hmma(float* __restrict__ Cout)
{
    extern __shared__ __align__(16) char dsm[];
    const uint32_t sbase = smem_u32(dsm);

    const int tid  = threadIdx.x;
    const int wid  = tid >> 5;
    const int lane = tid & 31;
    const int wy = wid >> 2;
    const int wx = wid & 3;
    const int g = lane >> 2;
    const int t = lane & 3;
    const int m0 = blockIdx.y * 128;
    const int n0 = blockIdx.x * 128;

    const __nv_bfloat16* __restrict__ Ah = (MODE == 0) ? g_in_h  : g_ctx_h;
    const __nv_bfloat16* __restrict__ Al = (MODE == 0) ? g_in_l  : g_ctx_l;
    const __nv_bfloat16* __restrict__ Bh = (MODE == 0) ? g_win_h : g_wout_h;
    const __nv_bfloat16* __restrict__ Bl = (MODE == 0) ? g_win_l : g_wout_l;

    // per-thread load slots: 2 chunks per matrix
    const int r0c = tid >> 2, ck0 = (tid & 3);
    const int r1c = (256 + tid) >> 2, ck1 = ((256 + tid) & 3);

    auto issue_stage = [&](int k0, uint32_t sb) {
        {
            const size_t ga = (size_t)(m0 + r0c) * KDIM + k0 + ck0 * 8;
            const size_t gb = (size_t)(n0 + r0c) * KDIM + k0 + ck0 * 8;
            const uint32_t off = (uint32_t)(r0c * RS + ck0 * 8) * 2;
            cp16(sb + off,        Ah + ga);
            cp16(sb + G_AL + off, Al + ga);
            cp16(sb + G_BH + off, Bh + gb);
            cp16(sb + G_BL + off, Bl + gb);
        }
        {
            const size_t ga = (size_t)(m0 + r1c) * KDIM + k0 + ck1 * 8;
            const size_t gb = (size_t)(n0 + r1c) * KDIM + k0 + ck1 * 8;
            const uint32_t off = (uint32_t)(r1c * RS + ck1 * 8) * 2;
            cp16(sb + off,        Ah + ga);
            cp16(sb + G_AL + off, Al + ga);
            cp16(sb + G_BH + off, Bh + gb);
            cp16(sb + G_BL + off, Bl + gb);
        }
        CP_COMMIT();
    };

    float acc[4][4][4];
#pragma unroll
    for (int mi = 0; mi < 4; mi++)
#pragma unroll
        for (int nj = 0; nj < 4; nj++)
#pragma unroll
            for (int q = 0; q < 4; q++) acc[mi][nj][q] = 0.f;

    const int lrow = lane & 15;
    const int lcol = (lane >> 4) << 3;

    // prologue: stages 0 and 1
    issue_stage(0, sbase);
    issue_stage(32, sbase + G_STAGE);

    const int NIT = KDIM / 32;   // 32
    for (int i = 0; i < NIT; i++) {
        if (i < NIT - 1) { CP_WAIT(1); } else { CP_WAIT(0); }
        __syncthreads();
        if (i + 2 < NIT)
            issue_stage((i + 2) * 32, sbase + ((i + 2) % 3) * G_STAGE);

        const uint32_t sb = sbase + (i % 3) * G_STAGE;
#pragma unroll
        for (int ks = 0; ks < 2; ks++) {
            const int kc = ks * 16 + lcol;
            uint32_t fah[4][4], fal[4][4];
#pragma unroll
            for (int mi = 0; mi < 4; mi++) {
                const uint32_t ad = sb + ((wy * 64 + mi * 16 + lrow) * RS + kc) * 2;
                ldsm_x4(fah[mi], ad);
                ldsm_x4(fal[mi], ad + G_AL);
            }
            uint32_t fbh[2][4], fbl[2][4];
#pragma unroll
            for (int p = 0; p < 2; p++) {
                const uint32_t bd = sb + G_BH + ((wx * 32 + p * 16 + lrow) * RS + kc) * 2;
                ldsm_x4(fbh[p], bd);
                ldsm_x4(fbl[p], bd + (G_BL - G_BH));
            }
#pragma unroll
            for (int mi = 0; mi < 4; mi++)
#pragma unroll
                for (int nj = 0; nj < 4; nj++) {
                    const int p = nj >> 1, o = nj & 1;
                    mma_bf16(acc[mi][nj], fah[mi][0], fah[mi][1], fah[mi][2], fah[mi][3],
                             fbh[p][o], fbh[p][o + 2]);
                    mma_bf16(acc[mi][nj], fah[mi][0], fah[mi][1], fah[mi][2], fah[mi][3],
                             fbl[p][o], fbl[p][o + 2]);
                    mma_bf16(acc[mi][nj], fal[mi][0], fal[mi][1], fal[mi][2], fal[mi][3],
                             fbh[p][o], fbh[p][o + 2]);
                }
        }
    }

    // ---- epilogue
#pragma unroll
    for (int mi = 0; mi < 4; mi++) {
        const int row0 = m0 + wy * 64 + mi * 16 + g;
        const int row1 = row0 + 8;
#pragma unroll
        for (int nj = 0; nj < 4; nj++) {
            const int col = n0 + wx * 32 + nj * 8 + 2 * t;
            if (MODE == 1) {
                *(float2*)&Cout[(size_t)row0 * CDIM + col] =
                    make_float2(acc[mi][nj][0], acc[mi][nj][1]);
                *(float2*)&Cout[(size_t)row1 * CDIM + col] =
                    make_float2(acc[mi][nj][2], acc[mi][nj][3]);
            } else {
                const int which = col >> 10;
                __nv_bfloat16* dh = (which == 0) ? g_qh : ((which == 1) ? g_kh : g_vh);
                __nv_bfloat16* dl = (which == 0) ? g_ql : ((which == 1) ? g_kl : g_vl);
                const int hh = (col & 1023) >> 6;
                const int dd = col & 63;
                uint32_t hi, lo;
                pack_split2(acc[mi][nj][0], acc[mi][nj][1], hi, lo);
                {
                    const int br = row0 >> 11, lr2 = row0 & 2047;
                    const size_t idx = (((size_t)(br * NHEAD + hh)) * LSEQ + lr2) * DHEAD + dd;
                    *(uint32_t*)(dh + idx) = hi;
                    *(uint32_t*)(dl + idx) = lo;
                }
                pack_split2(acc[mi][nj][2], acc[mi][nj][3], hi, lo);
                {
                    const int br = row1 >> 11, lr2 = row1 & 2047;
                    const size_t idx = (((size_t)(br * NHEAD + hh)) * LSEQ + lr2) * DHEAD + dd;
                    *(uint32_t*)(dh + idx) = hi;
                    *(uint32_t*)(dl + idx) = lo;
                }
            }
        }
    }
}

// ---------------------------------------------------------------------------
// HMMA causal flash attention with 3-stage cp.async K/V pipeline.
// Br=128, Bc=64, 256 threads (8 warps). grid: (B*H, L/128) qtile reversed.
// Smem (bytes): QH 0, QL 18432; KV stages at 36864 + s*36864:
//   per stage KH 0, KL 9216, VH 18432, VL 27648.
// ---------------------------------------------------------------------------
#define ARS 72
#define AQ_L 18432
#define AKV0 36864
#define A_KL 9216
#define A_VH 18432
#define A_VL 27648
#define A_STAGE 36864
#define SMEM_ATTN (AKV0 + 3 * A_STAGE)    // 147456

__global__ __launch_bounds__(256, 1) void attn_hmma()
{
    extern __shared__ __align__(16) char dsa[];
    const uint32_t sbase = smem_u32(dsa);

    const int tid  = threadIdx.x;
    const int w    = tid >> 5;
    const int lane = tid & 31;
    const int g = lane >> 2;
    const int t = lane & 3;
    const int lrow = lane & 15;
    const int lcol = (lane >> 4) << 3;

    const int bh = blockIdx.x;
    const int qt = (int)gridDim.y - 1 - (int)blockIdx.y;
    const int qbase = qt * 128;

    const size_t hoff = (size_t)bh * LSEQ * DHEAD;
    const __nv_bfloat16* __restrict__ Qh = g_qh + hoff;
    const __nv_bfloat16* __restrict__ Ql = g_ql + hoff;
    const __nv_bfloat16* __restrict__ Kh = g_kh + hoff;
    const __nv_bfloat16* __restrict__ Kl = g_kl + hoff;
    const __nv_bfloat16* __restrict__ Vh = g_vh + hoff;
    const __nv_bfloat16* __restrict__ Vl = g_vl + hoff;

    const int nkt = 2 * qt + 2;

    auto issue_kv = [&](int kt, uint32_t sb) {
#pragma unroll
        for (int it = 0; it < 2; it++) {
            const int s = it * 256 + tid;
            const int r = s >> 3, ck = s & 7;
            const size_t go = (size_t)(kt * 64 + r) * DHEAD + ck * 8;
            const uint32_t off = (uint32_t)(r * ARS + ck * 8) * 2;
            cp16(sb + off,        Kh + go);
            cp16(sb + A_KL + off, Kl + go);
            cp16(sb + A_VH + off, Vh + go);
            cp16(sb + A_VL + off, Vl + go);
        }
        CP_COMMIT();
    };

    // group 0: Q tile (128x64 hi/lo)
#pragma unroll
    for (int it = 0; it < 4; it++) {
        const int s = it * 256 + tid;
        const int r = s >> 3, ck = s & 7;
        const size_t go = (size_t)(qbase + r) * DHEAD + ck * 8;
        const uint32_t off = (uint32_t)(r * ARS + ck * 8) * 2;
        cp16(sbase + off,        Qh + go);
        cp16(sbase + AQ_L + off, Ql + go);
    }
    CP_COMMIT();
    // groups 1,2: KV stages 0,1
    issue_kv(0, sbase + AKV0);
    issue_kv(1, sbase + AKV0 + A_STAGE);

    // wait for Q (allow 2 KV groups pending), load Q fragments
    CP_WAIT(2);
    __syncthreads();
    uint32_t qfh[4][4], qfl[4][4];
#pragma unroll
    for (int ks = 0; ks < 4; ks++) {
        const uint32_t ad = sbase + ((w * 16 + lrow) * ARS + ks * 16 + lcol) * 2;
        ldsm_x4(qfh[ks], ad);
        ldsm_x4(qfl[ks], ad + AQ_L);
    }

    float O[8][4];
#pragma unroll
    for (int j = 0; j < 8; j++)
#pragma unroll
        for (int q = 0; q < 4; q++) O[j][q] = 0.f;
    float m0 = -1e30f, m1 = -1e30f, l0 = 0.f, l1 = 0.f;
    const float scale = 0.125f;
    const int row0 = qbase + w * 16 + g;
    const int row1 = row0 + 8;

    for (int kt = 0; kt < nkt; kt++) {
        const int kbase = kt * 64;

        if (kt + 1 < nkt) { CP_WAIT(1); } else { CP_WAIT(0); }
        __syncthreads();
        if (kt + 2 < nkt)
            issue_kv(kt + 2, sbase + AKV0 + ((kt + 2) % 3) * A_STAGE);

        const uint32_t sb = sbase + AKV0 + (kt % 3) * A_STAGE;

        // ---- S = Q K^T (3-term split)
        float S[8][4];
#pragma unroll
        for (int j = 0; j < 8; j++)
#pragma unroll
            for (int q = 0; q < 4; q++) S[j][q] = 0.f;

#pragma unroll
        for (int ks = 0; ks < 4; ks++) {
#pragma unroll
            for (int p = 0; p < 4; p++) {
                uint32_t kh0[4], kl0[4];
                const uint32_t bd = sb + ((p * 16 + lrow) * ARS + ks * 16 + lcol) * 2;
                ldsm_x4(kh0, bd);
                ldsm_x4(kl0, bd + A_KL);
#pragma unroll
                for (int o = 0; o < 2; o++) {
                    const int j = 2 * p + o;
                    mma_bf16(S[j], qfh[ks][0], qfh[ks][1], qfh[ks][2], qfh[ks][3],
                             kh0[o], kh0[o + 2]);
                    mma_bf16(S[j], qfh[ks][0], qfh[ks][1], qfh[ks][2], qfh[ks][3],
                             kl0[o], kl0[o + 2]);
                    mma_bf16(S[j], qfl[ks][0], qfl[ks][1], qfl[ks][2], qfl[ks][3],
                             kh0[o], kh0[o + 2]);
                }
            }
        }

        // ---- causal mask on diagonal tiles
        if (kt >= nkt - 2) {
#pragma unroll
            for (int j = 0; j < 8; j++) {
                const int col = kbase + j * 8 + 2 * t;
                if (col > row0)     S[j][0] = -1e30f;
                if (col + 1 > row0) S[j][1] = -1e30f;
                if (col > row1)     S[j][2] = -1e30f;
                if (col + 1 > row1) S[j][3] = -1e30f;
            }
        }

        // ---- online softmax
        float mt0 = -1e30f, mt1 = -1e30f;
#pragma unroll
        for (int j = 0; j < 8; j++) {
            mt0 = fmaxf(mt0, fmaxf(S[j][0], S[j][1]));
            mt1 = fmaxf(mt1, fmaxf(S[j][2], S[j][3]));
        }
        mt0 = fmaxf(mt0, __shfl_xor_sync(0xffffffffu, mt0, 1));
        mt0 = fmaxf(mt0, __shfl_xor_sync(0xffffffffu, mt0, 2));
        mt1 = fmaxf(mt1, __shfl_xor_sync(0xffffffffu, mt1, 1));
        mt1 = fmaxf(mt1, __shfl_xor_sync(0xffffffffu, mt1, 2));
        const float mn0 = fmaxf(m0, mt0 * scale);
        const float mn1 = fmaxf(m1, mt1 * scale);
        const float a0 = __expf(m0 - mn0);
        const float a1 = __expf(m1 - mn1);
        m0 = mn0; m1 = mn1;

        float rs0 = 0.f, rs1 = 0.f;
#pragma unroll
        for (int j = 0; j < 8; j++) {
            S[j][0] = __expf(fmaf(S[j][0], scale, -mn0));
            S[j][1] = __expf(fmaf(S[j][1], scale, -mn0));
            S[j][2] = __expf(fmaf(S[j][2], scale, -mn1));
            S[j][3] = __expf(fmaf(S[j][3], scale, -mn1));
            rs0 += S[j][0] + S[j][1];
            rs1 += S[j][2] + S[j][3];
        }
        rs0 += __shfl_xor_sync(0xffffffffu, rs0, 1);
        rs0 += __shfl_xor_sync(0xffffffffu, rs0, 2);
        rs1 += __shfl_xor_sync(0xffffffffu, rs1, 1);
        rs1 += __shfl_xor_sync(0xffffffffu, rs1, 2);
        l0 = l0 * a0 + rs0;
        l1 = l1 * a1 + rs1;
#pragma unroll
        for (int j = 0; j < 8; j++) {
            O[j][0] *= a0; O[j][1] *= a0;
            O[j][2] *= a1; O[j][3] *= a1;
        }

        // ---- O += P V (3-term split)
#pragma unroll
        for (int jj = 0; jj < 4; jj++) {
            uint32_t ah[4], al[4];
            pack_split2(S[2 * jj][0],     S[2 * jj][1],     ah[0], al[0]);
            pack_split2(S[2 * jj][2],     S[2 * jj][3],     ah[1], al[1]);
            pack_split2(S[2 * jj + 1][0], S[2 * jj + 1][1], ah[2], al[2]);
            pack_split2(S[2 * jj + 1][2], S[2 * jj + 1][3], ah[3], al[3]);
#pragma unroll
            for (int p = 0; p < 4; p++) {
                uint32_t vh0[4], vl0[4];
                const uint32_t vd = sb + A_VH + ((jj * 16 + lrow) * ARS + p * 16 + lcol) * 2;
                ldsm_x4_t(vh0, vd);
                ldsm_x4_t(vl0, vd + (A_VL - A_VH));
#pragma unroll
                for (int o = 0; o < 2; o++) {
                    const int j2 = 2 * p + o;
                    mma_bf16(O[j2], ah[0], ah[1], ah[2], ah[3], vh0[2 * o], vh0[2 * o + 1]);
                    mma_bf16(O[j2], ah[0], ah[1], ah[2], ah[3], vl0[2 * o], vl0[2 * o + 1]);
                    mma_bf16(O[j2], al[0], al[1], al[2], al[3], vh0[2 * o], vh0[2 * o + 1]);
                }
            }
        }
    }

    // ---- finalize
    const int b = bh >> 4;
    const int h = bh & 15;
    const float i0 = 1.f / l0;
    const float i1 = 1.f / l1;
#pragma unroll
    for (int j = 0; j < 8; j++) {
        const int col = h * DHEAD + j * 8 + 2 * t;
        uint32_t hi, lo;
        pack_split2(O[j][0] * i0, O[j][1] * i0, hi, lo);
        {
            const size_t idx = ((size_t)(b * LSEQ + row0)) * CDIM + col;
            *(uint32_t*)(g_ctx_h + idx) = hi;
            *(uint32_t*)(g_ctx_l + idx) = lo;
        }
        pack_split2(O[j][2] * i1, O[j][3] * i1, hi, lo);
        {
            const size_t idx = ((size_t)(b * LSEQ + row1)) * CDIM + col;
            *(uint32_t*)(g_ctx_h + idx) = hi;
            *(uint32_t*)(g_ctx_l + idx) = lo;
        }
    }
}

// ---------------------------------------------------------------------------
extern "C" void kernel_launch(void* const* d_in, const int* in_sizes, int n_in,
                              void* d_out, int out_size)
{
    const float* input = (const float*)d_in[0];
    const float* w_in  = (const float*)d_in[1];
    const float* w_out = (const float*)d_in[2];
    float* out = (float*)d_out;

    cudaFuncSetAttribute(gemm_hmma<0>, cudaFuncAttributeMaxDynamicSharedMemorySize, SMEM_GEMM);
    cudaFuncSetAttribute(gemm_hmma<1>, cudaFuncAttributeMaxDynamicSharedMemorySize, SMEM_GEMM);
    cudaFuncSetAttribute(attn_hmma,    cudaFuncAttributeMaxDynamicSharedMemorySize, SMEM_ATTN);

    cvt_kernel<<<(MROWS * KDIM / 4) / 256, 256>>>(input, MROWS * KDIM / 4, 0);
    cvt_kernel<<<(3 * CDIM * KDIM / 4) / 256, 256>>>(w_in, 3 * CDIM * KDIM / 4, 1);
    cvt_kernel<<<(CDIM * KDIM / 4) / 256, 256>>>(w_out, CDIM * KDIM / 4, 2);

    gemm_hmma<0><<<dim3(3 * CDIM / 128, MROWS / 128), 256, SMEM_GEMM>>>(nullptr);
    attn_hmma<<<dim3(BATCH * NHEAD, LSEQ / 128), 256, SMEM_ATTN>>>();
    gemm_hmma<1><<<dim3(CDIM / 128, MROWS / 128), 256, SMEM_GEMM>>>(out);
}

// round 6
// speedup vs baseline: 2.6221x; 1.0218x over previous
#include <cuda_runtime.h>
#include <cuda_bf16.h>
#include <cstdint>

// ---------------------------------------------------------------------------
// Problem constants
// ---------------------------------------------------------------------------
#define BATCH 4
#define LSEQ  2048
#define CDIM  1024
#define NHEAD 16
#define DHEAD 64
#define MROWS (BATCH * LSEQ)   // 8192
#define KDIM  1024

// ---------------------------------------------------------------------------
// Device-global scratch (allocation-free per harness rules)
// ---------------------------------------------------------------------------
__device__ __nv_bfloat16 g_in_h [MROWS * KDIM];
__device__ __nv_bfloat16 g_in_l [MROWS * KDIM];
__device__ __nv_bfloat16 g_win_h[3 * CDIM * KDIM];
__device__ __nv_bfloat16 g_win_l[3 * CDIM * KDIM];
__device__ __nv_bfloat16 g_wout_h[CDIM * KDIM];
__device__ __nv_bfloat16 g_wout_l[CDIM * KDIM];
__device__ __nv_bfloat16 g_qh[BATCH * NHEAD * LSEQ * DHEAD];
__device__ __nv_bfloat16 g_ql[BATCH * NHEAD * LSEQ * DHEAD];
__device__ __nv_bfloat16 g_kh[BATCH * NHEAD * LSEQ * DHEAD];
__device__ __nv_bfloat16 g_kl[BATCH * NHEAD * LSEQ * DHEAD];
__device__ __nv_bfloat16 g_vh[BATCH * NHEAD * LSEQ * DHEAD];
__device__ __nv_bfloat16 g_vl[BATCH * NHEAD * LSEQ * DHEAD];
__device__ __nv_bfloat16 g_ctx_h[MROWS * CDIM];
__device__ __nv_bfloat16 g_ctx_l[MROWS * CDIM];

// ---------------------------------------------------------------------------
// Baseline-PTX helpers (compute_103-safe: mma.sync, ldmatrix, cp.async)
// ---------------------------------------------------------------------------
__device__ __forceinline__ uint32_t smem_u32(const void* p) {
    uint32_t a;
    asm("{ .reg .u64 t; cvta.to.shared.u64 t, %1; cvt.u32.u64 %0, t; }"
        : "=r"(a) : "l"(p));
    return a;
}
__device__ __forceinline__ void ldsm_x4(uint32_t r[4], uint32_t addr) {
    asm volatile("ldmatrix.sync.aligned.m8n8.x4.shared.b16 {%0,%1,%2,%3}, [%4];"
                 : "=r"(r[0]), "=r"(r[1]), "=r"(r[2]), "=r"(r[3]) : "r"(addr));
}
__device__ __forceinline__ void ldsm_x4_t(uint32_t r[4], uint32_t addr) {
    asm volatile("ldmatrix.sync.aligned.m8n8.x4.trans.shared.b16 {%0,%1,%2,%3}, [%4];"
                 : "=r"(r[0]), "=r"(r[1]), "=r"(r[2]), "=r"(r[3]) : "r"(addr));
}
__device__ __forceinline__ void mma_bf16(float c[4],
                                         uint32_t a0, uint32_t a1, uint32_t a2, uint32_t a3,
                                         uint32_t b0, uint32_t b1) {
    asm volatile(
        "mma.sync.aligned.m16n8k16.row.col.f32.bf16.bf16.f32 "
        "{%0,%1,%2,%3}, {%4,%5,%6,%7}, {%8,%9}, {%0,%1,%2,%3};"
        : "+f"(c[0]), "+f"(c[1]), "+f"(c[2]), "+f"(c[3])
        : "r"(a0), "r"(a1), "r"(a2), "r"(a3), "r"(b0), "r"(b1));
}
__device__ __forceinline__ void cp16(uint32_t dst, const void* src) {
    asm volatile("cp.async.cg.shared.global [%0], [%1], 16;" :: "r"(dst), "l"(src));
}
#define CP_COMMIT() asm volatile("cp.async.commit_group;" ::: "memory")
#define CP_WAIT(N)  asm volatile("cp.async.wait_group %0;" :: "n"(N) : "memory")

__device__ __forceinline__ void split_bf16(float x, __nv_bfloat16& h, __nv_bfloat16& l) {
    h = __float2bfloat16(x);
    l = __float2bfloat16(x - __bfloat162float(h));
}
__device__ __forceinline__ void pack_split2(float x, float y, uint32_t& hi, uint32_t& lo) {
    __nv_bfloat162 h = __floats2bfloat162_rn(x, y);
    float2 hf = __bfloat1622float2(h);
    __nv_bfloat162 l = __floats2bfloat162_rn(x - hf.x, y - hf.y);
    hi = *(uint32_t*)&h;
    lo = *(uint32_t*)&l;
}

// ---------------------------------------------------------------------------
// fp32 -> (bf16 hi, bf16 lo) conversion
// ---------------------------------------------------------------------------
__global__ __launch_bounds__(256) void cvt_kernel(const float* __restrict__ src,
                                                  int n4, int sel)
{
    int i = blockIdx.x * blockDim.x + threadIdx.x;
    if (i >= n4) return;
    __nv_bfloat16* hp;
    __nv_bfloat16* lp;
    if (sel == 0)      { hp = g_in_h;   lp = g_in_l;  }
    else if (sel == 1) { hp = g_win_h;  lp = g_win_l; }
    else               { hp = g_wout_h; lp = g_wout_l; }
    float4 v = ((const float4*)src)[i];
    __nv_bfloat16 h0, h1, h2, h3, l0, l1, l2, l3;
    split_bf16(v.x, h0, l0); split_bf16(v.y, h1, l1);
    split_bf16(v.z, h2, l2); split_bf16(v.w, h3, l3);
    __nv_bfloat162 a, b;
    a.x = h0; a.y = h1; b.x = h2; b.y = h3;
    *(__nv_bfloat162*)(hp + 4 * (size_t)i)     = a;
    *(__nv_bfloat162*)(hp + 4 * (size_t)i + 2) = b;
    a.x = l0; a.y = l1; b.x = l2; b.y = l3;
    *(__nv_bfloat162*)(lp + 4 * (size_t)i)     = a;
    *(__nv_bfloat162*)(lp + 4 * (size_t)i + 2) = b;
}

// ---------------------------------------------------------------------------
// HMMA split-bf16 NT GEMM with 3-stage cp.async pipeline.
// BM=BN=128, BK=32, 512 threads (16 warps, 4x4 grid), warp tile 32x32.
// Stage layout (bytes): AH 0, AL 10240, BH 20480, BL 30720; stage = 40960.
// ---------------------------------------------------------------------------
#define RS 40                             // row stride in halves (80 B)
#define G_AL 10240
#define G_BH 20480
#define G_BL 30720
#define G_STAGE 40960
#define SMEM_GEMM (3 * G_STAGE)           // 122880

template <int MODE>
__global__ __launch_bounds__(512, 1) void gemm_hmma(float* __restrict__ Cout)
{
    extern __shared__ __align__(16) char dsm[];
    const uint32_t sbase = smem_u32(dsm);

    const int tid  = threadIdx.x;
    const int wid  = tid >> 5;
    const int lane = tid & 31;
    const int wy = wid >> 2;            // 0..3 (m)
    const int wx = wid & 3;             // 0..3 (n)
    const int g = lane >> 2;
    const int t = lane & 3;
    const int m0 = blockIdx.y * 128;
    const int n0 = blockIdx.x * 128;

    const __nv_bfloat16* __restrict__ Ah = (MODE == 0) ? g_in_h  : g_ctx_h;
    const __nv_bfloat16* __restrict__ Al = (MODE == 0) ? g_in_l  : g_ctx_l;
    const __nv_bfloat16* __restrict__ Bh = (MODE == 0) ? g_win_h : g_wout_h;
    const __nv_bfloat16* __restrict__ Bl = (MODE == 0) ? g_win_l : g_wout_l;

    // loader: one 16B chunk per matrix per thread (128 rows x 4 chunks)
    const int rl = tid >> 2, ckl = tid & 3;

    auto issue_stage = [&](int k0, uint32_t sb) {
        const size_t ga = (size_t)(m0 + rl) * KDIM + k0 + ckl * 8;
        const size_t gb = (size_t)(n0 + rl) * KDIM + k0 + ckl * 8;
        const uint32_t off = (uint32_t)(rl * RS + ckl * 8) * 2;
        cp16(sb + off,        Ah + ga);
        cp16(sb + G_AL + off, Al + ga);
        cp16(sb + G_BH + off, Bh + gb);
        cp16(sb + G_BL + off, Bl + gb);
        CP_COMMIT();
    };

    float acc[2][4][4];
#pragma unroll
    for (int mi = 0; mi < 2; mi++)
#pragma unroll
        for (int nj = 0; nj < 4; nj++)
#pragma unroll
            for (int q = 0; q < 4; q++) acc[mi][nj][q] = 0.f;

    const int lrow = lane & 15;
    const int lcol = (lane >> 4) << 3;

    // prologue: stages 0 and 1
    issue_stage(0, sbase);
    issue_stage(32, sbase + G_STAGE);

    const int NIT = KDIM / 32;   // 32
    for (int i = 0; i < NIT; i++) {
        if (i < NIT - 1) { CP_WAIT(1); } else { CP_WAIT(0); }
        __syncthreads();
        if (i + 2 < NIT)
            issue_stage((i + 2) * 32, sbase + ((i + 2) % 3) * G_STAGE);

        const uint32_t sb = sbase + (i % 3) * G_STAGE;
#pragma unroll
        for (int ks = 0; ks < 2; ks++) {
            const int kc = ks * 16 + lcol;
            uint32_t fah[2][4], fal[2][4];
#pragma unroll
            for (int mi = 0; mi < 2; mi++) {
                const uint32_t ad = sb + ((wy * 32 + mi * 16 + lrow) * RS + kc) * 2;
                ldsm_x4(fah[mi], ad);
                ldsm_x4(fal[mi], ad + G_AL);
            }
            uint32_t fbh[2][4], fbl[2][4];
#pragma unroll
            for (int p = 0; p < 2; p++) {
                const uint32_t bd = sb + G_BH + ((wx * 32 + p * 16 + lrow) * RS + kc) * 2;
                ldsm_x4(fbh[p], bd);
                ldsm_x4(fbl[p], bd + (G_BL - G_BH));
            }
#pragma unroll
            for (int mi = 0; mi < 2; mi++)
#pragma unroll
                for (int nj = 0; nj < 4; nj++) {
                    const int p = nj >> 1, o = nj & 1;
                    mma_bf16(acc[mi][nj], fah[mi][0], fah[mi][1], fah[mi][2], fah[mi][3],
                             fbh[p][o], fbh[p][o + 2]);
                    mma_bf16(acc[mi][nj], fah[mi][0], fah[mi][1], fah[mi][2], fah[mi][3],
                             fbl[p][o], fbl[p][o + 2]);
                    mma_bf16(acc[mi][nj], fal[mi][0], fal[mi][1], fal[mi][2], fal[mi][3],
                             fbh[p][o], fbh[p][o + 2]);
                }
        }
    }

    // ---- epilogue
#pragma unroll
    for (int mi = 0; mi < 2; mi++) {
        const int row0 = m0 + wy * 32 + mi * 16 + g;
        const int row1 = row0 + 8;
#pragma unroll
        for (int nj = 0; nj < 4; nj++) {
            const int col = n0 + wx * 32 + nj * 8 + 2 * t;
            if (MODE == 1) {
                *(float2*)&Cout[(size_t)row0 * CDIM + col] =
                    make_float2(acc[mi][nj][0], acc[mi][nj][1]);
                *(float2*)&Cout[(size_t)row1 * CDIM + col] =
                    make_float2(acc[mi][nj][2], acc[mi][nj][3]);
            } else {
                const int which = col >> 10;
                __nv_bfloat16* dh = (which == 0) ? g_qh : ((which == 1) ? g_kh : g_vh);
                __nv_bfloat16* dl = (which == 0) ? g_ql : ((which == 1) ? g_kl : g_vl);
                const int hh = (col & 1023) >> 6;
                const int dd = col & 63;
                uint32_t hi, lo;
                pack_split2(acc[mi][nj][0], acc[mi][nj][1], hi, lo);
                {
                    const int br = row0 >> 11, lr2 = row0 & 2047;
                    const size_t idx = (((size_t)(br * NHEAD + hh)) * LSEQ + lr2) * DHEAD + dd;
                    *(uint32_t*)(dh + idx) = hi;
                    *(uint32_t*)(dl + idx) = lo;
                }
                pack_split2(acc[mi][nj][2], acc[mi][nj][3], hi, lo);
                {
                    const int br = row1 >> 11, lr2 = row1 & 2047;
                    const size_t idx = (((size_t)(br * NHEAD + hh)) * LSEQ + lr2) * DHEAD + dd;
                    *(uint32_t*)(dh + idx) = hi;
                    *(uint32_t*)(dl + idx) = lo;
                }
            }
        }
    }
}

// ---------------------------------------------------------------------------
// HMMA causal flash attention with 3-stage cp.async K/V pipeline.
// Br=128, Bc=64, 256 threads (8 warps). grid: (B*H, L/128) qtile reversed.
// ---------------------------------------------------------------------------
#define ARS 72
#define AQ_L 18432
#define AKV0 36864
#define A_KL 9216
#define A_VH 18432
#define A_VL 27648
#define A_STAGE 36864
#define SMEM_ATTN (AKV0 + 3 * A_STAGE)    // 147456

__global__ __launch_bounds__(256, 1) void attn_hmma()
{
    extern __shared__ __align__(16) char dsa[];
    const uint32_t sbase = smem_u32(dsa);

    const int tid  = threadIdx.x;
    const int w    = tid >> 5;
    const int lane = tid & 31;
    const int g = lane >> 2;
    const int t = lane & 3;
    const int lrow = lane & 15;
    const int lcol = (lane >> 4) << 3;

    const int bh = blockIdx.x;
    const int qt = (int)gridDim.y - 1 - (int)blockIdx.y;
    const int qbase = qt * 128;

    const size_t hoff = (size_t)bh * LSEQ * DHEAD;
    const __nv_bfloat16* __restrict__ Qh = g_qh + hoff;
    const __nv_bfloat16* __restrict__ Ql = g_ql + hoff;
    const __nv_bfloat16* __restrict__ Kh = g_kh + hoff;
    const __nv_bfloat16* __restrict__ Kl = g_kl + hoff;
    const __nv_bfloat16* __restrict__ Vh = g_vh + hoff;
    const __nv_bfloat16* __restrict__ Vl = g_vl + hoff;

    const int nkt = 2 * qt + 2;

    auto issue_kv = [&](int kt, uint32_t sb) {
#pragma unroll
        for (int it = 0; it < 2; it++) {
            const int s = it * 256 + tid;
            const int r = s >> 3, ck = s & 7;
            const size_t go = (size_t)(kt * 64 + r) * DHEAD + ck * 8;
            const uint32_t off = (uint32_t)(r * ARS + ck * 8) * 2;
            cp16(sb + off,        Kh + go);
            cp16(sb + A_KL + off, Kl + go);
            cp16(sb + A_VH + off, Vh + go);
            cp16(sb + A_VL + off, Vl + go);
        }
        CP_COMMIT();
    };

    // group 0: Q tile (128x64 hi/lo)
#pragma unroll
    for (int it = 0; it < 4; it++) {
        const int s = it * 256 + tid;
        const int r = s >> 3, ck = s & 7;
        const size_t go = (size_t)(qbase + r) * DHEAD + ck * 8;
        const uint32_t off = (uint32_t)(r * ARS + ck * 8) * 2;
        cp16(sbase + off,        Qh + go);
        cp16(sbase + AQ_L + off, Ql + go);
    }
    CP_COMMIT();
    issue_kv(0, sbase + AKV0);
    issue_kv(1, sbase + AKV0 + A_STAGE);

    CP_WAIT(2);
    __syncthreads();
    uint32_t qfh[4][4], qfl[4][4];
#pragma unroll
    for (int ks = 0; ks < 4; ks++) {
        const uint32_t ad = sbase + ((w * 16 + lrow) * ARS + ks * 16 + lcol) * 2;
        ldsm_x4(qfh[ks], ad);
        ldsm_x4(qfl[ks], ad + AQ_L);
    }

    float O[8][4];
#pragma unroll
    for (int j = 0; j < 8; j++)
#pragma unroll
        for (int q = 0; q < 4; q++) O[j][q] = 0.f;
    float m0 = -1e30f, m1 = -1e30f, l0 = 0.f, l1 = 0.f;
    const float scale = 0.125f;
    const int row0 = qbase + w * 16 + g;
    const int row1 = row0 + 8;

    for (int kt = 0; kt < nkt; kt++) {
        const int kbase = kt * 64;

        if (kt + 1 < nkt) { CP_WAIT(1); } else { CP_WAIT(0); }
        __syncthreads();
        if (kt + 2 < nkt)
            issue_kv(kt + 2, sbase + AKV0 + ((kt + 2) % 3) * A_STAGE);

        const uint32_t sb = sbase + AKV0 + (kt % 3) * A_STAGE;

        // ---- S = Q K^T (3-term split)
        float S[8][4];
#pragma unroll
        for (int j = 0; j < 8; j++)
#pragma unroll
            for (int q = 0; q < 4; q++) S[j][q] = 0.f;

#pragma unroll
        for (int ks = 0; ks < 4; ks++) {
#pragma unroll
            for (int p = 0; p < 4; p++) {
                uint32_t kh0[4], kl0[4];
                const uint32_t bd = sb + ((p * 16 + lrow) * ARS + ks * 16 + lcol) * 2;
                ldsm_x4(kh0, bd);
                ldsm_x4(kl0, bd + A_KL);
#pragma unroll
                for (int o = 0; o < 2; o++) {
                    const int j = 2 * p + o;
                    mma_bf16(S[j], qfh[ks][0], qfh[ks][1], qfh[ks][2], qfh[ks][3],
                             kh0[o], kh0[o + 2]);
                    mma_bf16(S[j], qfh[ks][0], qfh[ks][1], qfh[ks][2], qfh[ks][3],
                             kl0[o], kl0[o + 2]);
                    mma_bf16(S[j], qfl[ks][0], qfl[ks][1], qfl[ks][2], qfl[ks][3],
                             kh0[o], kh0[o + 2]);
                }
            }
        }

        if (kt >= nkt - 2) {
#pragma unroll
            for (int j = 0; j < 8; j++) {
                const int col = kbase + j * 8 + 2 * t;
                if (col > row0)     S[j][0] = -1e30f;
                if (col + 1 > row0) S[j][1] = -1e30f;
                if (col > row1)     S[j][2] = -1e30f;
                if (col + 1 > row1) S[j][3] = -1e30f;
            }
        }

        // ---- online softmax
        float mt0 = -1e30f, mt1 = -1e30f;
#pragma unroll
        for (int j = 0; j < 8; j++) {
            mt0 = fmaxf(mt0, fmaxf(S[j][0], S[j][1]));
            mt1 = fmaxf(mt1, fmaxf(S[j][2], S[j][3]));
        }
        mt0 = fmaxf(mt0, __shfl_xor_sync(0xffffffffu, mt0, 1));
        mt0 = fmaxf(mt0, __shfl_xor_sync(0xffffffffu, mt0, 2));
        mt1 = fmaxf(mt1, __shfl_xor_sync(0xffffffffu, mt1, 1));
        mt1 = fmaxf(mt1, __shfl_xor_sync(0xffffffffu, mt1, 2));
        const float mn0 = fmaxf(m0, mt0 * scale);
        const float mn1 = fmaxf(m1, mt1 * scale);
        const float a0 = __expf(m0 - mn0);
        const float a1 = __expf(m1 - mn1);
        m0 = mn0; m1 = mn1;

        float rs0 = 0.f, rs1 = 0.f;
#pragma unroll
        for (int j = 0; j < 8; j++) {
            S[j][0] = __expf(fmaf(S[j][0], scale, -mn0));
            S[j][1] = __expf(fmaf(S[j][1], scale, -mn0));
            S[j][2] = __expf(fmaf(S[j][2], scale, -mn1));
            S[j][3] = __expf(fmaf(S[j][3], scale, -mn1));
            rs0 += S[j][0] + S[j][1];
            rs1 += S[j][2] + S[j][3];
        }
        rs0 += __shfl_xor_sync(0xffffffffu, rs0, 1);
        rs0 += __shfl_xor_sync(0xffffffffu, rs0, 2);
        rs1 += __shfl_xor_sync(0xffffffffu, rs1, 1);
        rs1 += __shfl_xor_sync(0xffffffffu, rs1, 2);
        l0 = l0 * a0 + rs0;
        l1 = l1 * a1 + rs1;
#pragma unroll
        for (int j = 0; j < 8; j++) {
            O[j][0] *= a0; O[j][1] *= a0;
            O[j][2] *= a1; O[j][3] *= a1;
        }

        // ---- O += P V (3-term split)
#pragma unroll
        for (int jj = 0; jj < 4; jj++) {
            uint32_t ah[4], al[4];
            pack_split2(S[2 * jj][0],     S[2 * jj][1],     ah[0], al[0]);
            pack_split2(S[2 * jj][2],     S[2 * jj][3],     ah[1], al[1]);
            pack_split2(S[2 * jj + 1][0], S[2 * jj + 1][1], ah[2], al[2]);
            pack_split2(S[2 * jj + 1][2], S[2 * jj + 1][3], ah[3], al[3]);
#pragma unroll
            for (int p = 0; p < 4; p++) {
                uint32_t vh0[4], vl0[4];
                const uint32_t vd = sb + A_VH + ((jj * 16 + lrow) * ARS + p * 16 + lcol) * 2;
                ldsm_x4_t(vh0, vd);
                ldsm_x4_t(vl0, vd + (A_VL - A_VH));
#pragma unroll
                for (int o = 0; o < 2; o++) {
                    const int j2 = 2 * p + o;
                    mma_bf16(O[j2], ah[0], ah[1], ah[2], ah[3], vh0[2 * o], vh0[2 * o + 1]);
                    mma_bf16(O[j2], ah[0], ah[1], ah[2], ah[3], vl0[2 * o], vl0[2 * o + 1]);
                    mma_bf16(O[j2], al[0], al[1], al[2], al[3], vh0[2 * o], vh0[2 * o + 1]);
                }
            }
        }
    }

    // ---- finalize
    const int b = bh >> 4;
    const int h = bh & 15;
    const float i0 = 1.f / l0;
    const float i1 = 1.f / l1;
#pragma unroll
    for (int j = 0; j < 8; j++) {
        const int col = h * DHEAD + j * 8 + 2 * t;
        uint32_t hi, lo;
        pack_split2(O[j][0] * i0, O[j][1] * i0, hi, lo);
        {
            const size_t idx = ((size_t)(b * LSEQ + row0)) * CDIM + col;
            *(uint32_t*)(g_ctx_h + idx) = hi;
            *(uint32_t*)(g_ctx_l + idx) = lo;
        }
        pack_split2(O[j][2] * i1, O[j][3] * i1, hi, lo);
        {
            const size_t idx = ((size_t)(b * LSEQ + row1)) * CDIM + col;
            *(uint32_t*)(g_ctx_h + idx) = hi;
            *(uint32_t*)(g_ctx_l + idx) = lo;
        }
    }
}

// ---------------------------------------------------------------------------
extern "C" void kernel_launch(void* const* d_in, const int* in_sizes, int n_in,
                              void* d_out, int out_size)
{
    const float* input = (const float*)d_in[0];
    const float* w_in  = (const float*)d_in[1];
    const float* w_out = (const float*)d_in[2];
    float* out = (float*)d_out;

    cudaFuncSetAttribute(gemm_hmma<0>, cudaFuncAttributeMaxDynamicSharedMemorySize, SMEM_GEMM);
    cudaFuncSetAttribute(gemm_hmma<1>, cudaFuncAttributeMaxDynamicSharedMemorySize, SMEM_GEMM);
    cudaFuncSetAttribute(attn_hmma,    cudaFuncAttributeMaxDynamicSharedMemorySize, SMEM_ATTN);

    cvt_kernel<<<(MROWS * KDIM / 4) / 256, 256>>>(input, MROWS * KDIM / 4, 0);
    cvt_kernel<<<(3 * CDIM * KDIM / 4) / 256, 256>>>(w_in, 3 * CDIM * KDIM / 4, 1);
    cvt_kernel<<<(CDIM * KDIM / 4) / 256, 256>>>(w_out, CDIM * KDIM / 4, 2);

    gemm_hmma<0><<<dim3(3 * CDIM / 128, MROWS / 128), 512, SMEM_GEMM>>>(nullptr);
    attn_hmma<<<dim3(BATCH * NHEAD, LSEQ / 128), 256, SMEM_ATTN>>>();
    gemm_hmma<1><<<dim3(CDIM / 128, MROWS / 128), 512, SMEM_GEMM>>>(out);
}

// round 7
// speedup vs baseline: 2.7259x; 1.0396x over previous
#include <cuda_runtime.h>
#include <cuda_bf16.h>
#include <cstdint>

// ---------------------------------------------------------------------------
// Problem constants
// ---------------------------------------------------------------------------
#define BATCH 4
#define LSEQ  2048
#define CDIM  1024
#define NHEAD 16
#define DHEAD 64
#define MROWS (BATCH * LSEQ)   // 8192
#define KDIM  1024

// ---------------------------------------------------------------------------
// Device-global scratch (allocation-free per harness rules)
// ---------------------------------------------------------------------------
__device__ __nv_bfloat16 g_in_h [MROWS * KDIM];
__device__ __nv_bfloat16 g_in_l [MROWS * KDIM];
__device__ __nv_bfloat16 g_win_h[3 * CDIM * KDIM];
__device__ __nv_bfloat16 g_win_l[3 * CDIM * KDIM];
__device__ __nv_bfloat16 g_wout_h[CDIM * KDIM];
__device__ __nv_bfloat16 g_wout_l[CDIM * KDIM];
__device__ __nv_bfloat16 g_qh[BATCH * NHEAD * LSEQ * DHEAD];
__device__ __nv_bfloat16 g_ql[BATCH * NHEAD * LSEQ * DHEAD];
__device__ __nv_bfloat16 g_kh[BATCH * NHEAD * LSEQ * DHEAD];
__device__ __nv_bfloat16 g_kl[BATCH * NHEAD * LSEQ * DHEAD];
__device__ __nv_bfloat16 g_vh[BATCH * NHEAD * LSEQ * DHEAD];
__device__ __nv_bfloat16 g_vl[BATCH * NHEAD * LSEQ * DHEAD];
__device__ __nv_bfloat16 g_ctx_h[MROWS * CDIM];
__device__ __nv_bfloat16 g_ctx_l[MROWS * CDIM];

// ---------------------------------------------------------------------------
// Baseline-PTX helpers (compute_103-safe: mma.sync, ldmatrix, cp.async)
// ---------------------------------------------------------------------------
__device__ __forceinline__ uint32_t smem_u32(const void* p) {
    uint32_t a;
    asm("{ .reg .u64 t; cvta.to.shared.u64 t, %1; cvt.u32.u64 %0, t; }"
        : "=r"(a) : "l"(p));
    return a;
}
__device__ __forceinline__ void ldsm_x4(uint32_t r[4], uint32_t addr) {
    asm volatile("ldmatrix.sync.aligned.m8n8.x4.shared.b16 {%0,%1,%2,%3}, [%4];"
                 : "=r"(r[0]), "=r"(r[1]), "=r"(r[2]), "=r"(r[3]) : "r"(addr));
}
__device__ __forceinline__ void ldsm_x4_t(uint32_t r[4], uint32_t addr) {
    asm volatile("ldmatrix.sync.aligned.m8n8.x4.trans.shared.b16 {%0,%1,%2,%3}, [%4];"
                 : "=r"(r[0]), "=r"(r[1]), "=r"(r[2]), "=r"(r[3]) : "r"(addr));
}
__device__ __forceinline__ void mma_bf16(float c[4],
                                         uint32_t a0, uint32_t a1, uint32_t a2, uint32_t a3,
                                         uint32_t b0, uint32_t b1) {
    asm volatile(
        "mma.sync.aligned.m16n8k16.row.col.f32.bf16.bf16.f32 "
        "{%0,%1,%2,%3}, {%4,%5,%6,%7}, {%8,%9}, {%0,%1,%2,%3};"
        : "+f"(c[0]), "+f"(c[1]), "+f"(c[2]), "+f"(c[3])
        : "r"(a0), "r"(a1), "r"(a2), "r"(a3), "r"(b0), "r"(b1));
}
__device__ __forceinline__ void cp16(uint32_t dst, const void* src) {
    asm volatile("cp.async.cg.shared.global [%0], [%1], 16;" :: "r"(dst), "l"(src));
}
#define CP_COMMIT() asm volatile("cp.async.commit_group;" ::: "memory")
#define CP_WAIT(N)  asm volatile("cp.async.wait_group %0;" :: "n"(N) : "memory")

__device__ __forceinline__ void split_bf16(float x, __nv_bfloat16& h, __nv_bfloat16& l) {
    h = __float2bfloat16(x);
    l = __float2bfloat16(x - __bfloat162float(h));
}
__device__ __forceinline__ void pack_split2(float x, float y, uint32_t& hi, uint32_t& lo) {
    __nv_bfloat162 h = __floats2bfloat162_rn(x, y);
    float2 hf = __bfloat1622float2(h);
    __nv_bfloat162 l = __floats2bfloat162_rn(x - hf.x, y - hf.y);
    hi = *(uint32_t*)&h;
    lo = *(uint32_t*)&l;
}

// ---------------------------------------------------------------------------
// fp32 -> (bf16 hi, bf16 lo) conversion
// ---------------------------------------------------------------------------
__global__ __launch_bounds__(256) void cvt_kernel(const float* __restrict__ src,
                                                  int n4, int sel)
{
    int i = blockIdx.x * blockDim.x + threadIdx.x;
    if (i >= n4) return;
    __nv_bfloat16* hp;
    __nv_bfloat16* lp;
    if (sel == 0)      { hp = g_in_h;   lp = g_in_l;  }
    else if (sel == 1) { hp = g_win_h;  lp = g_win_l; }
    else               { hp = g_wout_h; lp = g_wout_l; }
    float4 v = ((const float4*)src)[i];
    __nv_bfloat16 h0, h1, h2, h3, l0, l1, l2, l3;
    split_bf16(v.x, h0, l0); split_bf16(v.y, h1, l1);
    split_bf16(v.z, h2, l2); split_bf16(v.w, h3, l3);
    __nv_bfloat162 a, b;
    a.x = h0; a.y = h1; b.x = h2; b.y = h3;
    *(__nv_bfloat162*)(hp + 4 * (size_t)i)     = a;
    *(__nv_bfloat162*)(hp + 4 * (size_t)i + 2) = b;
    a.x = l0; a.y = l1; b.x = l2; b.y = l3;
    *(__nv_bfloat162*)(lp + 4 * (size_t)i)     = a;
    *(__nv_bfloat162*)(lp + 4 * (size_t)i + 2) = b;
}

// ---------------------------------------------------------------------------
// HMMA split-bf16 NT GEMM with 3-stage cp.async pipeline, 2 CTAs/SM.
// BM=64, BN=128, BK=32, 256 threads (8 warps, 2x4 grid), warp tile 32x32.
// Stage layout (bytes): AH 0, AL 5120, BH 10240, BL 20480; stage = 30720.
// ---------------------------------------------------------------------------
#define RS 40                             // row stride in halves (80 B)
#define G_AL 5120
#define G_BH 10240
#define G_BL 20480
#define G_STAGE 30720
#define SMEM_GEMM (3 * G_STAGE)           // 92160

template <int MODE>
__global__ __launch_bounds__(256, 2) void gemm_hmma(float* __restrict__ Cout)
{
    extern __shared__ __align__(16) char dsm[];
    const uint32_t sbase = smem_u32(dsm);

    const int tid  = threadIdx.x;
    const int wid  = tid >> 5;
    const int lane = tid & 31;
    const int wy = wid >> 2;            // 0..1 (m)
    const int wx = wid & 3;             // 0..3 (n)
    const int g = lane >> 2;
    const int t = lane & 3;
    const int m0 = blockIdx.y * 64;
    const int n0 = blockIdx.x * 128;

    const __nv_bfloat16* __restrict__ Ah = (MODE == 0) ? g_in_h  : g_ctx_h;
    const __nv_bfloat16* __restrict__ Al = (MODE == 0) ? g_in_l  : g_ctx_l;
    const __nv_bfloat16* __restrict__ Bh = (MODE == 0) ? g_win_h : g_wout_h;
    const __nv_bfloat16* __restrict__ Bl = (MODE == 0) ? g_win_l : g_wout_l;

    // loaders: A 64 rows x 4 chunks (1 slot/thread); B 128 rows x 4 (2 slots)
    const int ra = tid >> 2, cka = tid & 3;
    const int rb0 = tid >> 2, ckb0 = tid & 3;
    const int rb1 = (256 + tid) >> 2, ckb1 = (256 + tid) & 3;

    auto issue_stage = [&](int k0, uint32_t sb) {
        {
            const size_t ga = (size_t)(m0 + ra) * KDIM + k0 + cka * 8;
            const uint32_t off = (uint32_t)(ra * RS + cka * 8) * 2;
            cp16(sb + off,        Ah + ga);
            cp16(sb + G_AL + off, Al + ga);
        }
        {
            const size_t gb = (size_t)(n0 + rb0) * KDIM + k0 + ckb0 * 8;
            const uint32_t off = (uint32_t)(rb0 * RS + ckb0 * 8) * 2;
            cp16(sb + G_BH + off, Bh + gb);
            cp16(sb + G_BL + off, Bl + gb);
        }
        {
            const size_t gb = (size_t)(n0 + rb1) * KDIM + k0 + ckb1 * 8;
            const uint32_t off = (uint32_t)(rb1 * RS + ckb1 * 8) * 2;
            cp16(sb + G_BH + off, Bh + gb);
            cp16(sb + G_BL + off, Bl + gb);
        }
        CP_COMMIT();
    };

    float acc[2][4][4];
#pragma unroll
    for (int mi = 0; mi < 2; mi++)
#pragma unroll
        for (int nj = 0; nj < 4; nj++)
#pragma unroll
            for (int q = 0; q < 4; q++) acc[mi][nj][q] = 0.f;

    const int lrow = lane & 15;
    const int lcol = (lane >> 4) << 3;

    issue_stage(0, sbase);
    issue_stage(32, sbase + G_STAGE);

    const int NIT = KDIM / 32;   // 32
    for (int i = 0; i < NIT; i++) {
        if (i < NIT - 1) { CP_WAIT(1); } else { CP_WAIT(0); }
        __syncthreads();
        if (i + 2 < NIT)
            issue_stage((i + 2) * 32, sbase + ((i + 2) % 3) * G_STAGE);

        const uint32_t sb = sbase + (i % 3) * G_STAGE;
#pragma unroll
        for (int ks = 0; ks < 2; ks++) {
            const int kc = ks * 16 + lcol;
            uint32_t fah[2][4], fal[2][4];
#pragma unroll
            for (int mi = 0; mi < 2; mi++) {
                const uint32_t ad = sb + ((wy * 32 + mi * 16 + lrow) * RS + kc) * 2;
                ldsm_x4(fah[mi], ad);
                ldsm_x4(fal[mi], ad + G_AL);
            }
            uint32_t fbh[2][4], fbl[2][4];
#pragma unroll
            for (int p = 0; p < 2; p++) {
                const uint32_t bd = sb + G_BH + ((wx * 32 + p * 16 + lrow) * RS + kc) * 2;
                ldsm_x4(fbh[p], bd);
                ldsm_x4(fbl[p], bd + (G_BL - G_BH));
            }
#pragma unroll
            for (int mi = 0; mi < 2; mi++)
#pragma unroll
                for (int nj = 0; nj < 4; nj++) {
                    const int p = nj >> 1, o = nj & 1;
                    mma_bf16(acc[mi][nj], fah[mi][0], fah[mi][1], fah[mi][2], fah[mi][3],
                             fbh[p][o], fbh[p][o + 2]);
                    mma_bf16(acc[mi][nj], fah[mi][0], fah[mi][1], fah[mi][2], fah[mi][3],
                             fbl[p][o], fbl[p][o + 2]);
                    mma_bf16(acc[mi][nj], fal[mi][0], fal[mi][1], fal[mi][2], fal[mi][3],
                             fbh[p][o], fbh[p][o + 2]);
                }
        }
    }

    // ---- epilogue
#pragma unroll
    for (int mi = 0; mi < 2; mi++) {
        const int row0 = m0 + wy * 32 + mi * 16 + g;
        const int row1 = row0 + 8;
#pragma unroll
        for (int nj = 0; nj < 4; nj++) {
            const int col = n0 + wx * 32 + nj * 8 + 2 * t;
            if (MODE == 1) {
                *(float2*)&Cout[(size_t)row0 * CDIM + col] =
                    make_float2(acc[mi][nj][0], acc[mi][nj][1]);
                *(float2*)&Cout[(size_t)row1 * CDIM + col] =
                    make_float2(acc[mi][nj][2], acc[mi][nj][3]);
            } else {
                const int which = col >> 10;
                __nv_bfloat16* dh = (which == 0) ? g_qh : ((which == 1) ? g_kh : g_vh);
                __nv_bfloat16* dl = (which == 0) ? g_ql : ((which == 1) ? g_kl : g_vl);
                const int hh = (col & 1023) >> 6;
                const int dd = col & 63;
                uint32_t hi, lo;
                pack_split2(acc[mi][nj][0], acc[mi][nj][1], hi, lo);
                {
                    const int br = row0 >> 11, lr2 = row0 & 2047;
                    const size_t idx = (((size_t)(br * NHEAD + hh)) * LSEQ + lr2) * DHEAD + dd;
                    *(uint32_t*)(dh + idx) = hi;
                    *(uint32_t*)(dl + idx) = lo;
                }
                pack_split2(acc[mi][nj][2], acc[mi][nj][3], hi, lo);
                {
                    const int br = row1 >> 11, lr2 = row1 & 2047;
                    const size_t idx = (((size_t)(br * NHEAD + hh)) * LSEQ + lr2) * DHEAD + dd;
                    *(uint32_t*)(dh + idx) = hi;
                    *(uint32_t*)(dl + idx) = lo;
                }
            }
        }
    }
}

// ---------------------------------------------------------------------------
// HMMA causal flash attention with 3-stage cp.async K/V pipeline.
// Br=128, Bc=64, 256 threads (8 warps). grid: (B*H, L/128) qtile reversed.
// ---------------------------------------------------------------------------
#define ARS 72
#define AQ_L 18432
#define AKV0 36864
#define A_KL 9216
#define A_VH 18432
#define A_VL 27648
#define A_STAGE 36864
#define SMEM_ATTN (AKV0 + 3 * A_STAGE)    // 147456

__global__ __launch_bounds__(256, 1) void attn_hmma()
{
    extern __shared__ __align__(16) char dsa[];
    const uint32_t sbase = smem_u32(dsa);

    const int tid  = threadIdx.x;
    const int w    = tid >> 5;
    const int lane = tid & 31;
    const int g = lane >> 2;
    const int t = lane & 3;
    const int lrow = lane & 15;
    const int lcol = (lane >> 4) << 3;

    const int bh = blockIdx.x;
    const int qt = (int)gridDim.y - 1 - (int)blockIdx.y;
    const int qbase = qt * 128;

    const size_t hoff = (size_t)bh * LSEQ * DHEAD;
    const __nv_bfloat16* __restrict__ Qh = g_qh + hoff;
    const __nv_bfloat16* __restrict__ Ql = g_ql + hoff;
    const __nv_bfloat16* __restrict__ Kh = g_kh + hoff;
    const __nv_bfloat16* __restrict__ Kl = g_kl + hoff;
    const __nv_bfloat16* __restrict__ Vh = g_vh + hoff;
    const __nv_bfloat16* __restrict__ Vl = g_vl + hoff;

    const int nkt = 2 * qt + 2;

    auto issue_kv = [&](int kt, uint32_t sb) {
#pragma unroll
        for (int it = 0; it < 2; it++) {
            const int s = it * 256 + tid;
            const int r = s >> 3, ck = s & 7;
            const size_t go = (size_t)(kt * 64 + r) * DHEAD + ck * 8;
            const uint32_t off = (uint32_t)(r * ARS + ck * 8) * 2;
            cp16(sb + off,        Kh + go);
            cp16(sb + A_KL + off, Kl + go);
            cp16(sb + A_VH + off, Vh + go);
            cp16(sb + A_VL + off, Vl + go);
        }
        CP_COMMIT();
    };

    // group 0: Q tile (128x64 hi/lo)
#pragma unroll
    for (int it = 0; it < 4; it++) {
        const int s = it * 256 + tid;
        const int r = s >> 3, ck = s & 7;
        const size_t go = (size_t)(qbase + r) * DHEAD + ck * 8;
        const uint32_t off = (uint32_t)(r * ARS + ck * 8) * 2;
        cp16(sbase + off,        Qh + go);
        cp16(sbase + AQ_L + off, Ql + go);
    }
    CP_COMMIT();
    issue_kv(0, sbase + AKV0);
    issue_kv(1, sbase + AKV0 + A_STAGE);

    CP_WAIT(2);
    __syncthreads();
    uint32_t qfh[4][4], qfl[4][4];
#pragma unroll
    for (int ks = 0; ks < 4; ks++) {
        const uint32_t ad = sbase + ((w * 16 + lrow) * ARS + ks * 16 + lcol) * 2;
        ldsm_x4(qfh[ks], ad);
        ldsm_x4(qfl[ks], ad + AQ_L);
    }

    float O[8][4];
#pragma unroll
    for (int j = 0; j < 8; j++)
#pragma unroll
        for (int q = 0; q < 4; q++) O[j][q] = 0.f;
    float m0 = -1e30f, m1 = -1e30f, l0 = 0.f, l1 = 0.f;
    const float scale = 0.125f;
    const int row0 = qbase + w * 16 + g;
    const int row1 = row0 + 8;

    for (int kt = 0; kt < nkt; kt++) {
        const int kbase = kt * 64;

        if (kt + 1 < nkt) { CP_WAIT(1); } else { CP_WAIT(0); }
        __syncthreads();
        if (kt + 2 < nkt)
            issue_kv(kt + 2, sbase + AKV0 + ((kt + 2) % 3) * A_STAGE);

        const uint32_t sb = sbase + AKV0 + (kt % 3) * A_STAGE;

        float S[8][4];
#pragma unroll
        for (int j = 0; j < 8; j++)
#pragma unroll
            for (int q = 0; q < 4; q++) S[j][q] = 0.f;

#pragma unroll
        for (int ks = 0; ks < 4; ks++) {
#pragma unroll
            for (int p = 0; p < 4; p++) {
                uint32_t kh0[4], kl0[4];
                const uint32_t bd = sb + ((p * 16 + lrow) * ARS + ks * 16 + lcol) * 2;
                ldsm_x4(kh0, bd);
                ldsm_x4(kl0, bd + A_KL);
#pragma unroll
                for (int o = 0; o < 2; o++) {
                    const int j = 2 * p + o;
                    mma_bf16(S[j], qfh[ks][0], qfh[ks][1], qfh[ks][2], qfh[ks][3],
                             kh0[o], kh0[o + 2]);
                    mma_bf16(S[j], qfh[ks][0], qfh[ks][1], qfh[ks][2], qfh[ks][3],
                             kl0[o], kl0[o + 2]);
                    mma_bf16(S[j], qfl[ks][0], qfl[ks][1], qfl[ks][2], qfl[ks][3],
                             kh0[o], kh0[o + 2]);
                }
            }
        }

        if (kt >= nkt - 2) {
#pragma unroll
            for (int j = 0; j < 8; j++) {
                const int col = kbase + j * 8 + 2 * t;
                if (col > row0)     S[j][0] = -1e30f;
                if (col + 1 > row0) S[j][1] = -1e30f;
                if (col > row1)     S[j][2] = -1e30f;
                if (col + 1 > row1) S[j][3] = -1e30f;
            }
        }

        float mt0 = -1e30f, mt1 = -1e30f;
#pragma unroll
        for (int j = 0; j < 8; j++) {
            mt0 = fmaxf(mt0, fmaxf(S[j][0], S[j][1]));
            mt1 = fmaxf(mt1, fmaxf(S[j][2], S[j][3]));
        }
        mt0 = fmaxf(mt0, __shfl_xor_sync(0xffffffffu, mt0, 1));
        mt0 = fmaxf(mt0, __shfl_xor_sync(0xffffffffu, mt0, 2));
        mt1 = fmaxf(mt1, __shfl_xor_sync(0xffffffffu, mt1, 1));
        mt1 = fmaxf(mt1, __shfl_xor_sync(0xffffffffu, mt1, 2));
        const float mn0 = fmaxf(m0, mt0 * scale);
        const float mn1 = fmaxf(m1, mt1 * scale);
        const float a0 = __expf(m0 - mn0);
        const float a1 = __expf(m1 - mn1);
        m0 = mn0; m1 = mn1;

        float rs0 = 0.f, rs1 = 0.f;
#pragma unroll
        for (int j = 0; j < 8; j++) {
            S[j][0] = __expf(fmaf(S[j][0], scale, -mn0));
            S[j][1] = __expf(fmaf(S[j][1], scale, -mn0));
            S[j][2] = __expf(fmaf(S[j][2], scale, -mn1));
            S[j][3] = __expf(fmaf(S[j][3], scale, -mn1));
            rs0 += S[j][0] + S[j][1];
            rs1 += S[j][2] + S[j][3];
        }
        rs0 += __shfl_xor_sync(0xffffffffu, rs0, 1);
        rs0 += __shfl_xor_sync(0xffffffffu, rs0, 2);
        rs1 += __shfl_xor_sync(0xffffffffu, rs1, 1);
        rs1 += __shfl_xor_sync(0xffffffffu, rs1, 2);
        l0 = l0 * a0 + rs0;
        l1 = l1 * a1 + rs1;
#pragma unroll
        for (int j = 0; j < 8; j++) {
            O[j][0] *= a0; O[j][1] *= a0;
            O[j][2] *= a1; O[j][3] *= a1;
        }

#pragma unroll
        for (int jj = 0; jj < 4; jj++) {
            uint32_t ah[4], al[4];
            pack_split2(S[2 * jj][0],     S[2 * jj][1],     ah[0], al[0]);
            pack_split2(S[2 * jj][2],     S[2 * jj][3],     ah[1], al[1]);
            pack_split2(S[2 * jj + 1][0], S[2 * jj + 1][1], ah[2], al[2]);
            pack_split2(S[2 * jj + 1][2], S[2 * jj + 1][3], ah[3], al[3]);
#pragma unroll
            for (int p = 0; p < 4; p++) {
                uint32_t vh0[4], vl0[4];
                const uint32_t vd = sb + A_VH + ((jj * 16 + lrow) * ARS + p * 16 + lcol) * 2;
                ldsm_x4_t(vh0, vd);
                ldsm_x4_t(vl0, vd + (A_VL - A_VH));
#pragma unroll
                for (int o = 0; o < 2; o++) {
                    const int j2 = 2 * p + o;
                    mma_bf16(O[j2], ah[0], ah[1], ah[2], ah[3], vh0[2 * o], vh0[2 * o + 1]);
                    mma_bf16(O[j2], ah[0], ah[1], ah[2], ah[3], vl0[2 * o], vl0[2 * o + 1]);
                    mma_bf16(O[j2], al[0], al[1], al[2], al[3], vh0[2 * o], vh0[2 * o + 1]);
                }
            }
        }
    }

    const int b = bh >> 4;
    const int h = bh & 15;
    const float i0 = 1.f / l0;
    const float i1 = 1.f / l1;
#pragma unroll
    for (int j = 0; j < 8; j++) {
        const int col = h * DHEAD + j * 8 + 2 * t;
        uint32_t hi, lo;
        pack_split2(O[j][0] * i0, O[j][1] * i0, hi, lo);
        {
            const size_t idx = ((size_t)(b * LSEQ + row0)) * CDIM + col;
            *(uint32_t*)(g_ctx_h + idx) = hi;
            *(uint32_t*)(g_ctx_l + idx) = lo;
        }
        pack_split2(O[j][2] * i1, O[j][3] * i1, hi, lo);
        {
            const size_t idx = ((size_t)(b * LSEQ + row1)) * CDIM + col;
            *(uint32_t*)(g_ctx_h + idx) = hi;
            *(uint32_t*)(g_ctx_l + idx) = lo;
        }
    }
}

// ---------------------------------------------------------------------------
extern "C" void kernel_launch(void* const* d_in, const int* in_sizes, int n_in,
                              void* d_out, int out_size)
{
    const float* input = (const float*)d_in[0];
    const float* w_in  = (const float*)d_in[1];
    const float* w_out = (const float*)d_in[2];
    float* out = (float*)d_out;

    cudaFuncSetAttribute(gemm_hmma<0>, cudaFuncAttributeMaxDynamicSharedMemorySize, SMEM_GEMM);
    cudaFuncSetAttribute(gemm_hmma<1>, cudaFuncAttributeMaxDynamicSharedMemorySize, SMEM_GEMM);
    cudaFuncSetAttribute(attn_hmma,    cudaFuncAttributeMaxDynamicSharedMemorySize, SMEM_ATTN);

    cvt_kernel<<<(MROWS * KDIM / 4) / 256, 256>>>(input, MROWS * KDIM / 4, 0);
    cvt_kernel<<<(3 * CDIM * KDIM / 4) / 256, 256>>>(w_in, 3 * CDIM * KDIM / 4, 1);
    cvt_kernel<<<(CDIM * KDIM / 4) / 256, 256>>>(w_out, CDIM * KDIM / 4, 2);

    gemm_hmma<0><<<dim3(3 * CDIM / 128, MROWS / 64), 256, SMEM_GEMM>>>(nullptr);
    attn_hmma<<<dim3(BATCH * NHEAD, LSEQ / 128), 256, SMEM_ATTN>>>();
    gemm_hmma<1><<<dim3(CDIM / 128, MROWS / 64), 256, SMEM_GEMM>>>(out);
}

// round 8
// speedup vs baseline: 3.0163x; 1.1065x over previous
#include <cuda_runtime.h>
#include <cuda_bf16.h>
#include <cstdint>

// ---------------------------------------------------------------------------
// Problem constants
// ---------------------------------------------------------------------------
#define BATCH 4
#define LSEQ  2048
#define CDIM  1024
#define NHEAD 16
#define DHEAD 64
#define MROWS (BATCH * LSEQ)   // 8192
#define KDIM  1024

// ---------------------------------------------------------------------------
// Device-global scratch (allocation-free per harness rules)
// ---------------------------------------------------------------------------
__device__ __nv_bfloat16 g_in_h [MROWS * KDIM];
__device__ __nv_bfloat16 g_in_l [MROWS * KDIM];
__device__ __nv_bfloat16 g_win_h[3 * CDIM * KDIM];
__device__ __nv_bfloat16 g_win_l[3 * CDIM * KDIM];
__device__ __nv_bfloat16 g_wout_h[CDIM * KDIM];
__device__ __nv_bfloat16 g_wout_l[CDIM * KDIM];
__device__ __nv_bfloat16 g_qh[BATCH * NHEAD * LSEQ * DHEAD];
__device__ __nv_bfloat16 g_ql[BATCH * NHEAD * LSEQ * DHEAD];
__device__ __nv_bfloat16 g_kh[BATCH * NHEAD * LSEQ * DHEAD];
__device__ __nv_bfloat16 g_kl[BATCH * NHEAD * LSEQ * DHEAD];
__device__ __nv_bfloat16 g_vh[BATCH * NHEAD * LSEQ * DHEAD];
__device__ __nv_bfloat16 g_vl[BATCH * NHEAD * LSEQ * DHEAD];
__device__ __nv_bfloat16 g_ctx_h[MROWS * CDIM];
__device__ __nv_bfloat16 g_ctx_l[MROWS * CDIM];

// ---------------------------------------------------------------------------
// Baseline-PTX helpers (compute_103-safe: mma.sync, ldmatrix, cp.async)
// ---------------------------------------------------------------------------
__device__ __forceinline__ uint32_t smem_u32(const void* p) {
    uint32_t a;
    asm("{ .reg .u64 t; cvta.to.shared.u64 t, %1; cvt.u32.u64 %0, t; }"
        : "=r"(a) : "l"(p));
    return a;
}
__device__ __forceinline__ void ldsm_x4(uint32_t r[4], uint32_t addr) {
    asm volatile("ldmatrix.sync.aligned.m8n8.x4.shared.b16 {%0,%1,%2,%3}, [%4];"
                 : "=r"(r[0]), "=r"(r[1]), "=r"(r[2]), "=r"(r[3]) : "r"(addr));
}
__device__ __forceinline__ void ldsm_x4_t(uint32_t r[4], uint32_t addr) {
    asm volatile("ldmatrix.sync.aligned.m8n8.x4.trans.shared.b16 {%0,%1,%2,%3}, [%4];"
                 : "=r"(r[0]), "=r"(r[1]), "=r"(r[2]), "=r"(r[3]) : "r"(addr));
}
__device__ __forceinline__ void mma_bf16(float c[4],
                                         uint32_t a0, uint32_t a1, uint32_t a2, uint32_t a3,
                                         uint32_t b0, uint32_t b1) {
    asm volatile(
        "mma.sync.aligned.m16n8k16.row.col.f32.bf16.bf16.f32 "
        "{%0,%1,%2,%3}, {%4,%5,%6,%7}, {%8,%9}, {%0,%1,%2,%3};"
        : "+f"(c[0]), "+f"(c[1]), "+f"(c[2]), "+f"(c[3])
        : "r"(a0), "r"(a1), "r"(a2), "r"(a3), "r"(b0), "r"(b1));
}
__device__ __forceinline__ void cp16(uint32_t dst, const void* src) {
    asm volatile("cp.async.cg.shared.global [%0], [%1], 16;" :: "r"(dst), "l"(src));
}
#define CP_COMMIT() asm volatile("cp.async.commit_group;" ::: "memory")
#define CP_WAIT(N)  asm volatile("cp.async.wait_group %0;" :: "n"(N) : "memory")

__device__ __forceinline__ void split_bf16(float x, __nv_bfloat16& h, __nv_bfloat16& l) {
    h = __float2bfloat16(x);
    l = __float2bfloat16(x - __bfloat162float(h));
}
__device__ __forceinline__ void pack_split2(float x, float y, uint32_t& hi, uint32_t& lo) {
    __nv_bfloat162 h = __floats2bfloat162_rn(x, y);
    float2 hf = __bfloat1622float2(h);
    __nv_bfloat162 l = __floats2bfloat162_rn(x - hf.x, y - hf.y);
    hi = *(uint32_t*)&h;
    lo = *(uint32_t*)&l;
}

// ---------------------------------------------------------------------------
// fp32 -> (bf16 hi, bf16 lo) conversion
// ---------------------------------------------------------------------------
__global__ __launch_bounds__(256) void cvt_kernel(const float* __restrict__ src,
                                                  int n4, int sel)
{
    int i = blockIdx.x * blockDim.x + threadIdx.x;
    if (i >= n4) return;
    __nv_bfloat16* hp;
    __nv_bfloat16* lp;
    if (sel == 0)      { hp = g_in_h;   lp = g_in_l;  }
    else if (sel == 1) { hp = g_win_h;  lp = g_win_l; }
    else               { hp = g_wout_h; lp = g_wout_l; }
    float4 v = ((const float4*)src)[i];
    __nv_bfloat16 h0, h1, h2, h3, l0, l1, l2, l3;
    split_bf16(v.x, h0, l0); split_bf16(v.y, h1, l1);
    split_bf16(v.z, h2, l2); split_bf16(v.w, h3, l3);
    __nv_bfloat162 a, b;
    a.x = h0; a.y = h1; b.x = h2; b.y = h3;
    *(__nv_bfloat162*)(hp + 4 * (size_t)i)     = a;
    *(__nv_bfloat162*)(hp + 4 * (size_t)i + 2) = b;
    a.x = l0; a.y = l1; b.x = l2; b.y = l3;
    *(__nv_bfloat162*)(lp + 4 * (size_t)i)     = a;
    *(__nv_bfloat162*)(lp + 4 * (size_t)i + 2) = b;
}

// ---------------------------------------------------------------------------
// HMMA split-bf16 NT GEMM, BK=64, 2-stage cp.async buffer, 2 CTAs/SM.
// BM=64, BN=128, 256 threads (8 warps, 2x4 grid), warp tile 32x32.
// Per-stage layout (bytes): AH 0, AL 9216, BH 18432, BL 36864; stage 55296.
// Register double-buffered fragments across the 4 ks-steps.
// ---------------------------------------------------------------------------
#define RSH 72                            // row stride in halves (144 B)
#define G_AL 9216
#define G_BH 18432
#define G_BL 36864
#define G_STAGE 55296
#define SMEM_GEMM (2 * G_STAGE)           // 110592

template <int MODE>
__global__ __launch_bounds__(256, 2) void gemm_hmma(float* __restrict__ Cout)
{
    extern __shared__ __align__(16) char dsm[];
    const uint32_t sbase = smem_u32(dsm);

    const int tid  = threadIdx.x;
    const int wid  = tid >> 5;
    const int lane = tid & 31;
    const int wy = wid >> 2;            // 0..1 (m)
    const int wx = wid & 3;             // 0..3 (n)
    const int g = lane >> 2;
    const int t = lane & 3;
    const int m0 = blockIdx.y * 64;
    const int n0 = blockIdx.x * 128;

    const __nv_bfloat16* __restrict__ Ah = (MODE == 0) ? g_in_h  : g_ctx_h;
    const __nv_bfloat16* __restrict__ Al = (MODE == 0) ? g_in_l  : g_ctx_l;
    const __nv_bfloat16* __restrict__ Bh = (MODE == 0) ? g_win_h : g_wout_h;
    const __nv_bfloat16* __restrict__ Bl = (MODE == 0) ? g_win_l : g_wout_l;

    auto issue_stage = [&](int k0, uint32_t sb) {
#pragma unroll
        for (int u = 0; u < 2; u++) {                 // A: 64 rows x 8 chunks
            const int s = u * 256 + tid;
            const int r = s >> 3, ck = s & 7;
            const size_t ga = (size_t)(m0 + r) * KDIM + k0 + ck * 8;
            const uint32_t off = (uint32_t)(r * RSH + ck * 8) * 2;
            cp16(sb + off,        Ah + ga);
            cp16(sb + G_AL + off, Al + ga);
        }
#pragma unroll
        for (int u = 0; u < 4; u++) {                 // B: 128 rows x 8 chunks
            const int s = u * 256 + tid;
            const int r = s >> 3, ck = s & 7;
            const size_t gb = (size_t)(n0 + r) * KDIM + k0 + ck * 8;
            const uint32_t off = (uint32_t)(r * RSH + ck * 8) * 2;
            cp16(sb + G_BH + off, Bh + gb);
            cp16(sb + G_BL + off, Bl + gb);
        }
        CP_COMMIT();
    };

    float acc[2][4][4];
#pragma unroll
    for (int mi = 0; mi < 2; mi++)
#pragma unroll
        for (int nj = 0; nj < 4; nj++)
#pragma unroll
            for (int q = 0; q < 4; q++) acc[mi][nj][q] = 0.f;

    const int lrow = lane & 15;
    const int lcol = (lane >> 4) << 3;

    // fragment double buffers
    uint32_t fah[2][2][4], fal[2][2][4], fbh[2][2][4], fbl[2][2][4];

    auto ldfrags = [&](uint32_t sb, int ks, int b) {
        const int kc = ks * 16 + lcol;
#pragma unroll
        for (int mi = 0; mi < 2; mi++) {
            const uint32_t ad = sb + ((wy * 32 + mi * 16 + lrow) * RSH + kc) * 2;
            ldsm_x4(fah[b][mi], ad);
            ldsm_x4(fal[b][mi], ad + G_AL);
        }
#pragma unroll
        for (int p = 0; p < 2; p++) {
            const uint32_t bd = sb + G_BH + ((wx * 32 + p * 16 + lrow) * RSH + kc) * 2;
            ldsm_x4(fbh[b][p], bd);
            ldsm_x4(fbl[b][p], bd + (G_BL - G_BH));
        }
    };
    auto docompute = [&](int b) {
#pragma unroll
        for (int mi = 0; mi < 2; mi++)
#pragma unroll
            for (int nj = 0; nj < 4; nj++) {
                const int p = nj >> 1, o = nj & 1;
                mma_bf16(acc[mi][nj], fah[b][mi][0], fah[b][mi][1], fah[b][mi][2], fah[b][mi][3],
                         fbh[b][p][o], fbh[b][p][o + 2]);
                mma_bf16(acc[mi][nj], fah[b][mi][0], fah[b][mi][1], fah[b][mi][2], fah[b][mi][3],
                         fbl[b][p][o], fbl[b][p][o + 2]);
                mma_bf16(acc[mi][nj], fal[b][mi][0], fal[b][mi][1], fal[b][mi][2], fal[b][mi][3],
                         fbh[b][p][o], fbh[b][p][o + 2]);
            }
    };

    // prologue: stage 0 only (stage i+1 issued inside iter i)
    issue_stage(0, sbase);

    const int NIT = KDIM / 64;   // 16
    for (int i = 0; i < NIT; i++) {
        CP_WAIT(0);
        __syncthreads();
        const uint32_t sb = sbase + (i & 1) * G_STAGE;
        ldfrags(sb, 0, 0);
        if (i + 1 < NIT)
            issue_stage((i + 1) * 64, sbase + ((i + 1) & 1) * G_STAGE);
#pragma unroll
        for (int ks = 0; ks < 4; ks++) {
            if (ks < 3) ldfrags(sb, ks + 1, (ks + 1) & 1);
            docompute(ks & 1);
        }
    }

    // ---- epilogue
#pragma unroll
    for (int mi = 0; mi < 2; mi++) {
        const int row0 = m0 + wy * 32 + mi * 16 + g;
        const int row1 = row0 + 8;
#pragma unroll
        for (int nj = 0; nj < 4; nj++) {
            const int col = n0 + wx * 32 + nj * 8 + 2 * t;
            if (MODE == 1) {
                *(float2*)&Cout[(size_t)row0 * CDIM + col] =
                    make_float2(acc[mi][nj][0], acc[mi][nj][1]);
                *(float2*)&Cout[(size_t)row1 * CDIM + col] =
                    make_float2(acc[mi][nj][2], acc[mi][nj][3]);
            } else {
                const int which = col >> 10;
                __nv_bfloat16* dh = (which == 0) ? g_qh : ((which == 1) ? g_kh : g_vh);
                __nv_bfloat16* dl = (which == 0) ? g_ql : ((which == 1) ? g_kl : g_vl);
                const int hh = (col & 1023) >> 6;
                const int dd = col & 63;
                uint32_t hi, lo;
                pack_split2(acc[mi][nj][0], acc[mi][nj][1], hi, lo);
                {
                    const int br = row0 >> 11, lr2 = row0 & 2047;
                    const size_t idx = (((size_t)(br * NHEAD + hh)) * LSEQ + lr2) * DHEAD + dd;
                    *(uint32_t*)(dh + idx) = hi;
                    *(uint32_t*)(dl + idx) = lo;
                }
                pack_split2(acc[mi][nj][2], acc[mi][nj][3], hi, lo);
                {
                    const int br = row1 >> 11, lr2 = row1 & 2047;
                    const size_t idx = (((size_t)(br * NHEAD + hh)) * LSEQ + lr2) * DHEAD + dd;
                    *(uint32_t*)(dh + idx) = hi;
                    *(uint32_t*)(dl + idx) = lo;
                }
            }
        }
    }
}

// ---------------------------------------------------------------------------
// HMMA causal flash attention with 3-stage cp.async K/V pipeline (unchanged).
// Br=128, Bc=64, 256 threads (8 warps). grid: (B*H, L/128) qtile reversed.
// ---------------------------------------------------------------------------
#define ARS 72
#define AQ_L 18432
#define AKV0 36864
#define A_KL 9216
#define A_VH 18432
#define A_VL 27648
#define A_STAGE 36864
#define SMEM_ATTN (AKV0 + 3 * A_STAGE)    // 147456

__global__ __launch_bounds__(256, 1) void attn_hmma()
{
    extern __shared__ __align__(16) char dsa[];
    const uint32_t sbase = smem_u32(dsa);

    const int tid  = threadIdx.x;
    const int w    = tid >> 5;
    const int lane = tid & 31;
    const int g = lane >> 2;
    const int t = lane & 3;
    const int lrow = lane & 15;
    const int lcol = (lane >> 4) << 3;

    const int bh = blockIdx.x;
    const int qt = (int)gridDim.y - 1 - (int)blockIdx.y;
    const int qbase = qt * 128;

    const size_t hoff = (size_t)bh * LSEQ * DHEAD;
    const __nv_bfloat16* __restrict__ Qh = g_qh + hoff;
    const __nv_bfloat16* __restrict__ Ql = g_ql + hoff;
    const __nv_bfloat16* __restrict__ Kh = g_kh + hoff;
    const __nv_bfloat16* __restrict__ Kl = g_kl + hoff;
    const __nv_bfloat16* __restrict__ Vh = g_vh + hoff;
    const __nv_bfloat16* __restrict__ Vl = g_vl + hoff;

    const int nkt = 2 * qt + 2;

    auto issue_kv = [&](int kt, uint32_t sb) {
#pragma unroll
        for (int it = 0; it < 2; it++) {
            const int s = it * 256 + tid;
            const int r = s >> 3, ck = s & 7;
            const size_t go = (size_t)(kt * 64 + r) * DHEAD + ck * 8;
            const uint32_t off = (uint32_t)(r * ARS + ck * 8) * 2;
            cp16(sb + off,        Kh + go);
            cp16(sb + A_KL + off, Kl + go);
            cp16(sb + A_VH + off, Vh + go);
            cp16(sb + A_VL + off, Vl + go);
        }
        CP_COMMIT();
    };

#pragma unroll
    for (int it = 0; it < 4; it++) {
        const int s = it * 256 + tid;
        const int r = s >> 3, ck = s & 7;
        const size_t go = (size_t)(qbase + r) * DHEAD + ck * 8;
        const uint32_t off = (uint32_t)(r * ARS + ck * 8) * 2;
        cp16(sbase + off,        Qh + go);
        cp16(sbase + AQ_L + off, Ql + go);
    }
    CP_COMMIT();
    issue_kv(0, sbase + AKV0);
    issue_kv(1, sbase + AKV0 + A_STAGE);

    CP_WAIT(2);
    __syncthreads();
    uint32_t qfh[4][4], qfl[4][4];
#pragma unroll
    for (int ks = 0; ks < 4; ks++) {
        const uint32_t ad = sbase + ((w * 16 + lrow) * ARS + ks * 16 + lcol) * 2;
        ldsm_x4(qfh[ks], ad);
        ldsm_x4(qfl[ks], ad + AQ_L);
    }

    float O[8][4];
#pragma unroll
    for (int j = 0; j < 8; j++)
#pragma unroll
        for (int q = 0; q < 4; q++) O[j][q] = 0.f;
    float m0 = -1e30f, m1 = -1e30f, l0 = 0.f, l1 = 0.f;
    const float scale = 0.125f;
    const int row0 = qbase + w * 16 + g;
    const int row1 = row0 + 8;

    for (int kt = 0; kt < nkt; kt++) {
        const int kbase = kt * 64;

        if (kt + 1 < nkt) { CP_WAIT(1); } else { CP_WAIT(0); }
        __syncthreads();
        if (kt + 2 < nkt)
            issue_kv(kt + 2, sbase + AKV0 + ((kt + 2) % 3) * A_STAGE);

        const uint32_t sb = sbase + AKV0 + (kt % 3) * A_STAGE;

        float S[8][4];
#pragma unroll
        for (int j = 0; j < 8; j++)
#pragma unroll
            for (int q = 0; q < 4; q++) S[j][q] = 0.f;

#pragma unroll
        for (int ks = 0; ks < 4; ks++) {
#pragma unroll
            for (int p = 0; p < 4; p++) {
                uint32_t kh0[4], kl0[4];
                const uint32_t bd = sb + ((p * 16 + lrow) * ARS + ks * 16 + lcol) * 2;
                ldsm_x4(kh0, bd);
                ldsm_x4(kl0, bd + A_KL);
#pragma unroll
                for (int o = 0; o < 2; o++) {
                    const int j = 2 * p + o;
                    mma_bf16(S[j], qfh[ks][0], qfh[ks][1], qfh[ks][2], qfh[ks][3],
                             kh0[o], kh0[o + 2]);
                    mma_bf16(S[j], qfh[ks][0], qfh[ks][1], qfh[ks][2], qfh[ks][3],
                             kl0[o], kl0[o + 2]);
                    mma_bf16(S[j], qfl[ks][0], qfl[ks][1], qfl[ks][2], qfl[ks][3],
                             kh0[o], kh0[o + 2]);
                }
            }
        }

        if (kt >= nkt - 2) {
#pragma unroll
            for (int j = 0; j < 8; j++) {
                const int col = kbase + j * 8 + 2 * t;
                if (col > row0)     S[j][0] = -1e30f;
                if (col + 1 > row0) S[j][1] = -1e30f;
                if (col > row1)     S[j][2] = -1e30f;
                if (col + 1 > row1) S[j][3] = -1e30f;
            }
        }

        float mt0 = -1e30f, mt1 = -1e30f;
#pragma unroll
        for (int j = 0; j < 8; j++) {
            mt0 = fmaxf(mt0, fmaxf(S[j][0], S[j][1]));
            mt1 = fmaxf(mt1, fmaxf(S[j][2], S[j][3]));
        }
        mt0 = fmaxf(mt0, __shfl_xor_sync(0xffffffffu, mt0, 1));
        mt0 = fmaxf(mt0, __shfl_xor_sync(0xffffffffu, mt0, 2));
        mt1 = fmaxf(mt1, __shfl_xor_sync(0xffffffffu, mt1, 1));
        mt1 = fmaxf(mt1, __shfl_xor_sync(0xffffffffu, mt1, 2));
        const float mn0 = fmaxf(m0, mt0 * scale);
        const float mn1 = fmaxf(m1, mt1 * scale);
        const float a0 = __expf(m0 - mn0);
        const float a1 = __expf(m1 - mn1);
        m0 = mn0; m1 = mn1;

        float rs0 = 0.f, rs1 = 0.f;
#pragma unroll
        for (int j = 0; j < 8; j++) {
            S[j][0] = __expf(fmaf(S[j][0], scale, -mn0));
            S[j][1] = __expf(fmaf(S[j][1], scale, -mn0));
            S[j][2] = __expf(fmaf(S[j][2], scale, -mn1));
            S[j][3] = __expf(fmaf(S[j][3], scale, -mn1));
            rs0 += S[j][0] + S[j][1];
            rs1 += S[j][2] + S[j][3];
        }
        rs0 += __shfl_xor_sync(0xffffffffu, rs0, 1);
        rs0 += __shfl_xor_sync(0xffffffffu, rs0, 2);
        rs1 += __shfl_xor_sync(0xffffffffu, rs1, 1);
        rs1 += __shfl_xor_sync(0xffffffffu, rs1, 2);
        l0 = l0 * a0 + rs0;
        l1 = l1 * a1 + rs1;
#pragma unroll
        for (int j = 0; j < 8; j++) {
            O[j][0] *= a0; O[j][1] *= a0;
            O[j][2] *= a1; O[j][3] *= a1;
        }

#pragma unroll
        for (int jj = 0; jj < 4; jj++) {
            uint32_t ah[4], al[4];
            pack_split2(S[2 * jj][0],     S[2 * jj][1],     ah[0], al[0]);
            pack_split2(S[2 * jj][2],     S[2 * jj][3],     ah[1], al[1]);
            pack_split2(S[2 * jj + 1][0], S[2 * jj + 1][1], ah[2], al[2]);
            pack_split2(S[2 * jj + 1][2], S[2 * jj + 1][3], ah[3], al[3]);
#pragma unroll
            for (int p = 0; p < 4; p++) {
                uint32_t vh0[4], vl0[4];
                const uint32_t vd = sb + A_VH + ((jj * 16 + lrow) * ARS + p * 16 + lcol) * 2;
                ldsm_x4_t(vh0, vd);
                ldsm_x4_t(vl0, vd + (A_VL - A_VH));
#pragma unroll
                for (int o = 0; o < 2; o++) {
                    const int j2 = 2 * p + o;
                    mma_bf16(O[j2], ah[0], ah[1], ah[2], ah[3], vh0[2 * o], vh0[2 * o + 1]);
                    mma_bf16(O[j2], ah[0], ah[1], ah[2], ah[3], vl0[2 * o], vl0[2 * o + 1]);
                    mma_bf16(O[j2], al[0], al[1], al[2], al[3], vh0[2 * o], vh0[2 * o + 1]);
                }
            }
        }
    }

    const int b = bh >> 4;
    const int h = bh & 15;
    const float i0 = 1.f / l0;
    const float i1 = 1.f / l1;
#pragma unroll
    for (int j = 0; j < 8; j++) {
        const int col = h * DHEAD + j * 8 + 2 * t;
        uint32_t hi, lo;
        pack_split2(O[j][0] * i0, O[j][1] * i0, hi, lo);
        {
            const size_t idx = ((size_t)(b * LSEQ + row0)) * CDIM + col;
            *(uint32_t*)(g_ctx_h + idx) = hi;
            *(uint32_t*)(g_ctx_l + idx) = lo;
        }
        pack_split2(O[j][2] * i1, O[j][3] * i1, hi, lo);
        {
            const size_t idx = ((size_t)(b * LSEQ + row1)) * CDIM + col;
            *(uint32_t*)(g_ctx_h + idx) = hi;
            *(uint32_t*)(g_ctx_l + idx) = lo;
        }
    }
}

// ---------------------------------------------------------------------------
extern "C" void kernel_launch(void* const* d_in, const int* in_sizes, int n_in,
                              void* d_out, int out_size)
{
    const float* input = (const float*)d_in[0];
    const float* w_in  = (const float*)d_in[1];
    const float* w_out = (const float*)d_in[2];
    float* out = (float*)d_out;

    cudaFuncSetAttribute(gemm_hmma<0>, cudaFuncAttributeMaxDynamicSharedMemorySize, SMEM_GEMM);
    cudaFuncSetAttribute(gemm_hmma<1>, cudaFuncAttributeMaxDynamicSharedMemorySize, SMEM_GEMM);
    cudaFuncSetAttribute(attn_hmma,    cudaFuncAttributeMaxDynamicSharedMemorySize, SMEM_ATTN);

    cvt_kernel<<<(MROWS * KDIM / 4) / 256, 256>>>(input, MROWS * KDIM / 4, 0);
    cvt_kernel<<<(3 * CDIM * KDIM / 4) / 256, 256>>>(w_in, 3 * CDIM * KDIM / 4, 1);
    cvt_kernel<<<(CDIM * KDIM / 4) / 256, 256>>>(w_out, CDIM * KDIM / 4, 2);

    gemm_hmma<0><<<dim3(3 * CDIM / 128, MROWS / 64), 256, SMEM_GEMM>>>(nullptr);
    attn_hmma<<<dim3(BATCH * NHEAD, LSEQ / 128), 256, SMEM_ATTN>>>();
    gemm_hmma<1><<<dim3(CDIM / 128, MROWS / 64), 256, SMEM_GEMM>>>(out);
}

// round 9
// speedup vs baseline: 3.0725x; 1.0186x over previous
#include <cuda_runtime.h>
#include <cuda_bf16.h>
#include <cstdint>

// ---------------------------------------------------------------------------
// Problem constants
// ---------------------------------------------------------------------------
#define BATCH 4
#define LSEQ  2048
#define CDIM  1024
#define NHEAD 16
#define DHEAD 64
#define MROWS (BATCH * LSEQ)   // 8192
#define KDIM  1024

// ---------------------------------------------------------------------------
// Device-global scratch (allocation-free per harness rules)
// ---------------------------------------------------------------------------
__device__ __nv_bfloat16 g_in_h [MROWS * KDIM];
__device__ __nv_bfloat16 g_in_l [MROWS * KDIM];
__device__ __nv_bfloat16 g_win_h[3 * CDIM * KDIM];
__device__ __nv_bfloat16 g_win_l[3 * CDIM * KDIM];
__device__ __nv_bfloat16 g_wout_h[CDIM * KDIM];
__device__ __nv_bfloat16 g_wout_l[CDIM * KDIM];
__device__ __nv_bfloat16 g_qh[BATCH * NHEAD * LSEQ * DHEAD];
__device__ __nv_bfloat16 g_ql[BATCH * NHEAD * LSEQ * DHEAD];
__device__ __nv_bfloat16 g_kh[BATCH * NHEAD * LSEQ * DHEAD];
__device__ __nv_bfloat16 g_kl[BATCH * NHEAD * LSEQ * DHEAD];
__device__ __nv_bfloat16 g_vh[BATCH * NHEAD * LSEQ * DHEAD];
__device__ __nv_bfloat16 g_vl[BATCH * NHEAD * LSEQ * DHEAD];
__device__ __nv_bfloat16 g_ctx_h[MROWS * CDIM];
__device__ __nv_bfloat16 g_ctx_l[MROWS * CDIM];

// ---------------------------------------------------------------------------
// Baseline-PTX helpers (compute_103-safe: mma.sync, ldmatrix, cp.async)
// ---------------------------------------------------------------------------
__device__ __forceinline__ uint32_t smem_u32(const void* p) {
    uint32_t a;
    asm("{ .reg .u64 t; cvta.to.shared.u64 t, %1; cvt.u32.u64 %0, t; }"
        : "=r"(a) : "l"(p));
    return a;
}
__device__ __forceinline__ void ldsm_x4(uint32_t r[4], uint32_t addr) {
    asm volatile("ldmatrix.sync.aligned.m8n8.x4.shared.b16 {%0,%1,%2,%3}, [%4];"
                 : "=r"(r[0]), "=r"(r[1]), "=r"(r[2]), "=r"(r[3]) : "r"(addr));
}
__device__ __forceinline__ void ldsm_x4_t(uint32_t r[4], uint32_t addr) {
    asm volatile("ldmatrix.sync.aligned.m8n8.x4.trans.shared.b16 {%0,%1,%2,%3}, [%4];"
                 : "=r"(r[0]), "=r"(r[1]), "=r"(r[2]), "=r"(r[3]) : "r"(addr));
}
__device__ __forceinline__ void mma_bf16(float c[4],
                                         uint32_t a0, uint32_t a1, uint32_t a2, uint32_t a3,
                                         uint32_t b0, uint32_t b1) {
    asm volatile(
        "mma.sync.aligned.m16n8k16.row.col.f32.bf16.bf16.f32 "
        "{%0,%1,%2,%3}, {%4,%5,%6,%7}, {%8,%9}, {%0,%1,%2,%3};"
        : "+f"(c[0]), "+f"(c[1]), "+f"(c[2]), "+f"(c[3])
        : "r"(a0), "r"(a1), "r"(a2), "r"(a3), "r"(b0), "r"(b1));
}
__device__ __forceinline__ void cp16(uint32_t dst, const void* src) {
    asm volatile("cp.async.cg.shared.global [%0], [%1], 16;" :: "r"(dst), "l"(src));
}
#define CP_COMMIT() asm volatile("cp.async.commit_group;" ::: "memory")
#define CP_WAIT(N)  asm volatile("cp.async.wait_group %0;" :: "n"(N) : "memory")

__device__ __forceinline__ void split_bf16(float x, __nv_bfloat16& h, __nv_bfloat16& l) {
    h = __float2bfloat16(x);
    l = __float2bfloat16(x - __bfloat162float(h));
}
__device__ __forceinline__ void pack_split2(float x, float y, uint32_t& hi, uint32_t& lo) {
    __nv_bfloat162 h = __floats2bfloat162_rn(x, y);
    float2 hf = __bfloat1622float2(h);
    __nv_bfloat162 l = __floats2bfloat162_rn(x - hf.x, y - hf.y);
    hi = *(uint32_t*)&h;
    lo = *(uint32_t*)&l;
}

// ---------------------------------------------------------------------------
// fp32 -> (bf16 hi, bf16 lo) conversion — single fused launch.
// Ranges (in float4 units): input [0, 2097152), w_in [2097152, 2883584),
// w_out [2883584, 3145728).
// ---------------------------------------------------------------------------
#define CVT_N_IN   (MROWS * KDIM / 4)            // 2097152
#define CVT_N_WIN  (3 * CDIM * KDIM / 4)         //  786432
#define CVT_N_WOUT (CDIM * KDIM / 4)             //  262144
#define CVT_TOTAL  (CVT_N_IN + CVT_N_WIN + CVT_N_WOUT)

__global__ __launch_bounds__(256) void cvt_kernel(const float* __restrict__ in,
                                                  const float* __restrict__ w_in,
                                                  const float* __restrict__ w_out)
{
    int i = blockIdx.x * blockDim.x + threadIdx.x;
    if (i >= CVT_TOTAL) return;
    const float* src;
    __nv_bfloat16* hp;
    __nv_bfloat16* lp;
    int j;
    if (i < CVT_N_IN) {
        src = in;  hp = g_in_h;  lp = g_in_l;  j = i;
    } else if (i < CVT_N_IN + CVT_N_WIN) {
        src = w_in; hp = g_win_h; lp = g_win_l; j = i - CVT_N_IN;
    } else {
        src = w_out; hp = g_wout_h; lp = g_wout_l; j = i - CVT_N_IN - CVT_N_WIN;
    }
    float4 v = ((const float4*)src)[j];
    __nv_bfloat16 h0, h1, h2, h3, l0, l1, l2, l3;
    split_bf16(v.x, h0, l0); split_bf16(v.y, h1, l1);
    split_bf16(v.z, h2, l2); split_bf16(v.w, h3, l3);
    __nv_bfloat162 a, b;
    a.x = h0; a.y = h1; b.x = h2; b.y = h3;
    *(__nv_bfloat162*)(hp + 4 * (size_t)j)     = a;
    *(__nv_bfloat162*)(hp + 4 * (size_t)j + 2) = b;
    a.x = l0; a.y = l1; b.x = l2; b.y = l3;
    *(__nv_bfloat162*)(lp + 4 * (size_t)j)     = a;
    *(__nv_bfloat162*)(lp + 4 * (size_t)j + 2) = b;
}

// ---------------------------------------------------------------------------
// HMMA split-bf16 NT GEMM, BK=64, 2-stage cp.async buffer, 2 CTAs/SM.
// BM=64, BN=128, 256 threads (8 warps, 2x4 grid), warp tile 32x32.
// (unchanged from R8 — proven 55% tensor)
// ---------------------------------------------------------------------------
#define RSH 72                            // row stride in halves (144 B)
#define G_AL 9216
#define G_BH 18432
#define G_BL 36864
#define G_STAGE 55296
#define SMEM_GEMM (2 * G_STAGE)           // 110592

template <int MODE>
__global__ __launch_bounds__(256, 2) void gemm_hmma(float* __restrict__ Cout)
{
    extern __shared__ __align__(16) char dsm[];
    const uint32_t sbase = smem_u32(dsm);

    const int tid  = threadIdx.x;
    const int wid  = tid >> 5;
    const int lane = tid & 31;
    const int wy = wid >> 2;
    const int wx = wid & 3;
    const int g = lane >> 2;
    const int t = lane & 3;
    const int m0 = blockIdx.y * 64;
    const int n0 = blockIdx.x * 128;

    const __nv_bfloat16* __restrict__ Ah = (MODE == 0) ? g_in_h  : g_ctx_h;
    const __nv_bfloat16* __restrict__ Al = (MODE == 0) ? g_in_l  : g_ctx_l;
    const __nv_bfloat16* __restrict__ Bh = (MODE == 0) ? g_win_h : g_wout_h;
    const __nv_bfloat16* __restrict__ Bl = (MODE == 0) ? g_win_l : g_wout_l;

    auto issue_stage = [&](int k0, uint32_t sb) {
#pragma unroll
        for (int u = 0; u < 2; u++) {
            const int s = u * 256 + tid;
            const int r = s >> 3, ck = s & 7;
            const size_t ga = (size_t)(m0 + r) * KDIM + k0 + ck * 8;
            const uint32_t off = (uint32_t)(r * RSH + ck * 8) * 2;
            cp16(sb + off,        Ah + ga);
            cp16(sb + G_AL + off, Al + ga);
        }
#pragma unroll
        for (int u = 0; u < 4; u++) {
            const int s = u * 256 + tid;
            const int r = s >> 3, ck = s & 7;
            const size_t gb = (size_t)(n0 + r) * KDIM + k0 + ck * 8;
            const uint32_t off = (uint32_t)(r * RSH + ck * 8) * 2;
            cp16(sb + G_BH + off, Bh + gb);
            cp16(sb + G_BL + off, Bl + gb);
        }
        CP_COMMIT();
    };

    float acc[2][4][4];
#pragma unroll
    for (int mi = 0; mi < 2; mi++)
#pragma unroll
        for (int nj = 0; nj < 4; nj++)
#pragma unroll
            for (int q = 0; q < 4; q++) acc[mi][nj][q] = 0.f;

    const int lrow = lane & 15;
    const int lcol = (lane >> 4) << 3;

    uint32_t fah[2][2][4], fal[2][2][4], fbh[2][2][4], fbl[2][2][4];

    auto ldfrags = [&](uint32_t sb, int ks, int b) {
        const int kc = ks * 16 + lcol;
#pragma unroll
        for (int mi = 0; mi < 2; mi++) {
            const uint32_t ad = sb + ((wy * 32 + mi * 16 + lrow) * RSH + kc) * 2;
            ldsm_x4(fah[b][mi], ad);
            ldsm_x4(fal[b][mi], ad + G_AL);
        }
#pragma unroll
        for (int p = 0; p < 2; p++) {
            const uint32_t bd = sb + G_BH + ((wx * 32 + p * 16 + lrow) * RSH + kc) * 2;
            ldsm_x4(fbh[b][p], bd);
            ldsm_x4(fbl[b][p], bd + (G_BL - G_BH));
        }
    };
    auto docompute = [&](int b) {
#pragma unroll
        for (int mi = 0; mi < 2; mi++)
#pragma unroll
            for (int nj = 0; nj < 4; nj++) {
                const int p = nj >> 1, o = nj & 1;
                mma_bf16(acc[mi][nj], fah[b][mi][0], fah[b][mi][1], fah[b][mi][2], fah[b][mi][3],
                         fbh[b][p][o], fbh[b][p][o + 2]);
                mma_bf16(acc[mi][nj], fah[b][mi][0], fah[b][mi][1], fah[b][mi][2], fah[b][mi][3],
                         fbl[b][p][o], fbl[b][p][o + 2]);
                mma_bf16(acc[mi][nj], fal[b][mi][0], fal[b][mi][1], fal[b][mi][2], fal[b][mi][3],
                         fbh[b][p][o], fbh[b][p][o + 2]);
            }
    };

    issue_stage(0, sbase);

    const int NIT = KDIM / 64;   // 16
    for (int i = 0; i < NIT; i++) {
        CP_WAIT(0);
        __syncthreads();
        const uint32_t sb = sbase + (i & 1) * G_STAGE;
        ldfrags(sb, 0, 0);
        if (i + 1 < NIT)
            issue_stage((i + 1) * 64, sbase + ((i + 1) & 1) * G_STAGE);
#pragma unroll
        for (int ks = 0; ks < 4; ks++) {
            if (ks < 3) ldfrags(sb, ks + 1, (ks + 1) & 1);
            docompute(ks & 1);
        }
    }

    // ---- epilogue
#pragma unroll
    for (int mi = 0; mi < 2; mi++) {
        const int row0 = m0 + wy * 32 + mi * 16 + g;
        const int row1 = row0 + 8;
#pragma unroll
        for (int nj = 0; nj < 4; nj++) {
            const int col = n0 + wx * 32 + nj * 8 + 2 * t;
            if (MODE == 1) {
                *(float2*)&Cout[(size_t)row0 * CDIM + col] =
                    make_float2(acc[mi][nj][0], acc[mi][nj][1]);
                *(float2*)&Cout[(size_t)row1 * CDIM + col] =
                    make_float2(acc[mi][nj][2], acc[mi][nj][3]);
            } else {
                const int which = col >> 10;
                __nv_bfloat16* dh = (which == 0) ? g_qh : ((which == 1) ? g_kh : g_vh);
                __nv_bfloat16* dl = (which == 0) ? g_ql : ((which == 1) ? g_kl : g_vl);
                const int hh = (col & 1023) >> 6;
                const int dd = col & 63;
                uint32_t hi, lo;
                pack_split2(acc[mi][nj][0], acc[mi][nj][1], hi, lo);
                {
                    const int br = row0 >> 11, lr2 = row0 & 2047;
                    const size_t idx = (((size_t)(br * NHEAD + hh)) * LSEQ + lr2) * DHEAD + dd;
                    *(uint32_t*)(dh + idx) = hi;
                    *(uint32_t*)(dl + idx) = lo;
                }
                pack_split2(acc[mi][nj][2], acc[mi][nj][3], hi, lo);
                {
                    const int br = row1 >> 11, lr2 = row1 & 2047;
                    const size_t idx = (((size_t)(br * NHEAD + hh)) * LSEQ + lr2) * DHEAD + dd;
                    *(uint32_t*)(dh + idx) = hi;
                    *(uint32_t*)(dl + idx) = lo;
                }
            }
        }
    }
}

// ---------------------------------------------------------------------------
// HMMA causal flash attention, 2-stage cp.async K/V pipeline, 2 CTAs/SM.
// Br=128, Bc=64, 256 threads (8 warps). grid: (B*H, L/128) qtile reversed.
// Smem: QH 0, QL 18432; KV stages at 36864 + s*36864 (s in {0,1}).
// ---------------------------------------------------------------------------
#define ARS 72
#define AQ_L 18432
#define AKV0 36864
#define A_KL 9216
#define A_VH 18432
#define A_VL 27648
#define A_STAGE 36864
#define SMEM_ATTN (AKV0 + 2 * A_STAGE)    // 110592

__global__ __launch_bounds__(256, 2) void attn_hmma()
{
    extern __shared__ __align__(16) char dsa[];
    const uint32_t sbase = smem_u32(dsa);

    const int tid  = threadIdx.x;
    const int w    = tid >> 5;
    const int lane = tid & 31;
    const int g = lane >> 2;
    const int t = lane & 3;
    const int lrow = lane & 15;
    const int lcol = (lane >> 4) << 3;

    const int bh = blockIdx.x;
    const int qt = (int)gridDim.y - 1 - (int)blockIdx.y;
    const int qbase = qt * 128;

    const size_t hoff = (size_t)bh * LSEQ * DHEAD;
    const __nv_bfloat16* __restrict__ Qh = g_qh + hoff;
    const __nv_bfloat16* __restrict__ Ql = g_ql + hoff;
    const __nv_bfloat16* __restrict__ Kh = g_kh + hoff;
    const __nv_bfloat16* __restrict__ Kl = g_kl + hoff;
    const __nv_bfloat16* __restrict__ Vh = g_vh + hoff;
    const __nv_bfloat16* __restrict__ Vl = g_vl + hoff;

    const int nkt = 2 * qt + 2;

    auto issue_kv = [&](int kt, uint32_t sb) {
#pragma unroll
        for (int it = 0; it < 2; it++) {
            const int s = it * 256 + tid;
            const int r = s >> 3, ck = s & 7;
            const size_t go = (size_t)(kt * 64 + r) * DHEAD + ck * 8;
            const uint32_t off = (uint32_t)(r * ARS + ck * 8) * 2;
            cp16(sb + off,        Kh + go);
            cp16(sb + A_KL + off, Kl + go);
            cp16(sb + A_VH + off, Vh + go);
            cp16(sb + A_VL + off, Vl + go);
        }
        CP_COMMIT();
    };

    // Q tile (128x64 hi/lo) + KV stage 0
#pragma unroll
    for (int it = 0; it < 4; it++) {
        const int s = it * 256 + tid;
        const int r = s >> 3, ck = s & 7;
        const size_t go = (size_t)(qbase + r) * DHEAD + ck * 8;
        const uint32_t off = (uint32_t)(r * ARS + ck * 8) * 2;
        cp16(sbase + off,        Qh + go);
        cp16(sbase + AQ_L + off, Ql + go);
    }
    CP_COMMIT();
    issue_kv(0, sbase + AKV0);

    CP_WAIT(0);
    __syncthreads();
    uint32_t qfh[4][4], qfl[4][4];
#pragma unroll
    for (int ks = 0; ks < 4; ks++) {
        const uint32_t ad = sbase + ((w * 16 + lrow) * ARS + ks * 16 + lcol) * 2;
        ldsm_x4(qfh[ks], ad);
        ldsm_x4(qfl[ks], ad + AQ_L);
    }

    float O[8][4];
#pragma unroll
    for (int j = 0; j < 8; j++)
#pragma unroll
        for (int q = 0; q < 4; q++) O[j][q] = 0.f;
    float m0 = -1e30f, m1 = -1e30f, l0 = 0.f, l1 = 0.f;
    const float scale = 0.125f;
    const int row0 = qbase + w * 16 + g;
    const int row1 = row0 + 8;

    for (int kt = 0; kt < nkt; kt++) {
        const int kbase = kt * 64;

        CP_WAIT(0);
        __syncthreads();
        if (kt + 1 < nkt)
            issue_kv(kt + 1, sbase + AKV0 + ((kt + 1) & 1) * A_STAGE);

        const uint32_t sb = sbase + AKV0 + (kt & 1) * A_STAGE;

        // ---- S = Q K^T (3-term split)
        float S[8][4];
#pragma unroll
        for (int j = 0; j < 8; j++)
#pragma unroll
            for (int q = 0; q < 4; q++) S[j][q] = 0.f;

#pragma unroll
        for (int ks = 0; ks < 4; ks++) {
#pragma unroll
            for (int p = 0; p < 4; p++) {
                uint32_t kh0[4], kl0[4];
                const uint32_t bd = sb + ((p * 16 + lrow) * ARS + ks * 16 + lcol) * 2;
                ldsm_x4(kh0, bd);
                ldsm_x4(kl0, bd + A_KL);
#pragma unroll
                for (int o = 0; o < 2; o++) {
                    const int j = 2 * p + o;
                    mma_bf16(S[j], qfh[ks][0], qfh[ks][1], qfh[ks][2], qfh[ks][3],
                             kh0[o], kh0[o + 2]);
                    mma_bf16(S[j], qfh[ks][0], qfh[ks][1], qfh[ks][2], qfh[ks][3],
                             kl0[o], kl0[o + 2]);
                    mma_bf16(S[j], qfl[ks][0], qfl[ks][1], qfl[ks][2], qfl[ks][3],
                             kh0[o], kh0[o + 2]);
                }
            }
        }

        if (kt >= nkt - 2) {
#pragma unroll
            for (int j = 0; j < 8; j++) {
                const int col = kbase + j * 8 + 2 * t;
                if (col > row0)     S[j][0] = -1e30f;
                if (col + 1 > row0) S[j][1] = -1e30f;
                if (col > row1)     S[j][2] = -1e30f;
                if (col + 1 > row1) S[j][3] = -1e30f;
            }
        }

        float mt0 = -1e30f, mt1 = -1e30f;
#pragma unroll
        for (int j = 0; j < 8; j++) {
            mt0 = fmaxf(mt0, fmaxf(S[j][0], S[j][1]));
            mt1 = fmaxf(mt1, fmaxf(S[j][2], S[j][3]));
        }
        mt0 = fmaxf(mt0, __shfl_xor_sync(0xffffffffu, mt0, 1));
        mt0 = fmaxf(mt0, __shfl_xor_sync(0xffffffffu, mt0, 2));
        mt1 = fmaxf(mt1, __shfl_xor_sync(0xffffffffu, mt1, 1));
        mt1 = fmaxf(mt1, __shfl_xor_sync(0xffffffffu, mt1, 2));
        const float mn0 = fmaxf(m0, mt0 * scale);
        const float mn1 = fmaxf(m1, mt1 * scale);
        const float a0 = __expf(m0 - mn0);
        const float a1 = __expf(m1 - mn1);
        m0 = mn0; m1 = mn1;

        float rs0 = 0.f, rs1 = 0.f;
#pragma unroll
        for (int j = 0; j < 8; j++) {
            S[j][0] = __expf(fmaf(S[j][0], scale, -mn0));
            S[j][1] = __expf(fmaf(S[j][1], scale, -mn0));
            S[j][2] = __expf(fmaf(S[j][2], scale, -mn1));
            S[j][3] = __expf(fmaf(S[j][3], scale, -mn1));
            rs0 += S[j][0] + S[j][1];
            rs1 += S[j][2] + S[j][3];
        }
        rs0 += __shfl_xor_sync(0xffffffffu, rs0, 1);
        rs0 += __shfl_xor_sync(0xffffffffu, rs0, 2);
        rs1 += __shfl_xor_sync(0xffffffffu, rs1, 1);
        rs1 += __shfl_xor_sync(0xffffffffu, rs1, 2);
        l0 = l0 * a0 + rs0;
        l1 = l1 * a1 + rs1;
#pragma unroll
        for (int j = 0; j < 8; j++) {
            O[j][0] *= a0; O[j][1] *= a0;
            O[j][2] *= a1; O[j][3] *= a1;
        }

        // ---- O += P V (3-term split)
#pragma unroll
        for (int jj = 0; jj < 4; jj++) {
            uint32_t ah[4], al[4];
            pack_split2(S[2 * jj][0],     S[2 * jj][1],     ah[0], al[0]);
            pack_split2(S[2 * jj][2],     S[2 * jj][3],     ah[1], al[1]);
            pack_split2(S[2 * jj + 1][0], S[2 * jj + 1][1], ah[2], al[2]);
            pack_split2(S[2 * jj + 1][2], S[2 * jj + 1][3], ah[3], al[3]);
#pragma unroll
            for (int p = 0; p < 4; p++) {
                uint32_t vh0[4], vl0[4];
                const uint32_t vd = sb + A_VH + ((jj * 16 + lrow) * ARS + p * 16 + lcol) * 2;
                ldsm_x4_t(vh0, vd);
                ldsm_x4_t(vl0, vd + (A_VL - A_VH));
#pragma unroll
                for (int o = 0; o < 2; o++) {
                    const int j2 = 2 * p + o;
                    mma_bf16(O[j2], ah[0], ah[1], ah[2], ah[3], vh0[2 * o], vh0[2 * o + 1]);
                    mma_bf16(O[j2], ah[0], ah[1], ah[2], ah[3], vl0[2 * o], vl0[2 * o + 1]);
                    mma_bf16(O[j2], al[0], al[1], al[2], al[3], vh0[2 * o], vh0[2 * o + 1]);
                }
            }
        }
    }

    const int b = bh >> 4;
    const int h = bh & 15;
    const float i0 = 1.f / l0;
    const float i1 = 1.f / l1;
#pragma unroll
    for (int j = 0; j < 8; j++) {
        const int col = h * DHEAD + j * 8 + 2 * t;
        uint32_t hi, lo;
        pack_split2(O[j][0] * i0, O[j][1] * i0, hi, lo);
        {
            const size_t idx = ((size_t)(b * LSEQ + row0)) * CDIM + col;
            *(uint32_t*)(g_ctx_h + idx) = hi;
            *(uint32_t*)(g_ctx_l + idx) = lo;
        }
        pack_split2(O[j][2] * i1, O[j][3] * i1, hi, lo);
        {
            const size_t idx = ((size_t)(b * LSEQ + row1)) * CDIM + col;
            *(uint32_t*)(g_ctx_h + idx) = hi;
            *(uint32_t*)(g_ctx_l + idx) = lo;
        }
    }
}

// ---------------------------------------------------------------------------
extern "C" void kernel_launch(void* const* d_in, const int* in_sizes, int n_in,
                              void* d_out, int out_size)
{
    const float* input = (const float*)d_in[0];
    const float* w_in  = (const float*)d_in[1];
    const float* w_out = (const float*)d_in[2];
    float* out = (float*)d_out;

    cudaFuncSetAttribute(gemm_hmma<0>, cudaFuncAttributeMaxDynamicSharedMemorySize, SMEM_GEMM);
    cudaFuncSetAttribute(gemm_hmma<1>, cudaFuncAttributeMaxDynamicSharedMemorySize, SMEM_GEMM);
    cudaFuncSetAttribute(attn_hmma,    cudaFuncAttributeMaxDynamicSharedMemorySize, SMEM_ATTN);

    cvt_kernel<<<(CVT_TOTAL + 255) / 256, 256>>>(input, w_in, w_out);

    gemm_hmma<0><<<dim3(3 * CDIM / 128, MROWS / 64), 256, SMEM_GEMM>>>(nullptr);
    attn_hmma<<<dim3(BATCH * NHEAD, LSEQ / 128), 256, SMEM_ATTN>>>();
    gemm_hmma<1><<<dim3(CDIM / 128, MROWS / 64), 256, SMEM_GEMM>>>(out);
}